// round 1
// baseline (speedup 1.0000x reference)
#include <cuda_runtime.h>
#include <math.h>

#define Bz   4
#define Lz   1024
#define Dz   1024
#define Hz   16
#define HDz  64
#define Mz   (Bz*Lz)          // 4096
#define ORDERz 3

// Scratch (allocation-free rule: __device__ globals)
__device__ float g_q[Mz*Dz];     // (B,H,L,hd)
__device__ float g_k[Mz*Dz];     // (B,H,L,hd)
__device__ float g_v[Mz*Dz];     // (B,H,L,hd)
__device__ float g_ctx[Mz*Dz];   // (B,L,D)
__device__ float g_bias[Lz];

#define TM 64
#define TN 64
#define TK 32

// C[z] = scale * A[z] @ W[z]^T + bias[n]
// A: M x K row-major, W: N x K row-major. Batched via blockIdx.z.
// LAYOUT 0: C[m*N+n] row-major. LAYOUT 1: head layout (B,H,L,hd) from m=(b,l), n=(h,hd).
template<int LAYOUT>
__global__ __launch_bounds__(256) void gemm_nt(
    const float* __restrict__ A, const float* __restrict__ W,
    const float* __restrict__ bias, float* __restrict__ C,
    int M, int N, int K, float scale,
    long long strideA, long long strideW, long long strideC)
{
    __shared__ float As[TK][TM + 1];
    __shared__ float Ws[TK][TN + 1];

    const int z = blockIdx.z;
    A += (long long)z * strideA;
    W += (long long)z * strideW;
    C += (long long)z * strideC;

    const int bm = blockIdx.y * TM;
    const int bn = blockIdx.x * TN;
    const int tid = threadIdx.x;
    const int tx = tid & 15;      // 0..15 -> n micro
    const int ty = tid >> 4;      // 0..15 -> m micro

    float acc[4][4] = {};

    for (int k0 = 0; k0 < K; k0 += TK) {
        // 64x32 tiles, 2048 elems, 8 per thread. kk = lane -> conflict-free smem store.
        #pragma unroll
        for (int i = 0; i < 8; i++) {
            int idx = tid + i * 256;
            int r  = idx >> 5;
            int kk = idx & 31;
            As[kk][r] = A[(long long)(bm + r) * K + k0 + kk];
            Ws[kk][r] = W[(long long)(bn + r) * K + k0 + kk];
        }
        __syncthreads();
        #pragma unroll
        for (int kk = 0; kk < TK; kk++) {
            float a[4], w[4];
            #pragma unroll
            for (int i = 0; i < 4; i++) a[i] = As[kk][ty * 4 + i];
            #pragma unroll
            for (int j = 0; j < 4; j++) w[j] = Ws[kk][tx * 4 + j];
            #pragma unroll
            for (int i = 0; i < 4; i++)
                #pragma unroll
                for (int j = 0; j < 4; j++)
                    acc[i][j] = fmaf(a[i], w[j], acc[i][j]);
        }
        __syncthreads();
    }

    #pragma unroll
    for (int i = 0; i < 4; i++) {
        int m = bm + ty * 4 + i;
        #pragma unroll
        for (int j = 0; j < 4; j++) {
            int n = bn + tx * 4 + j;
            float v = acc[i][j] * scale + bias[n];
            if (LAYOUT == 0) {
                C[(long long)m * N + n] = v;
            } else {
                int b = m >> 10, l = m & 1023;
                int h = n >> 6,  dd = n & 63;
                C[(((long long)(b * Hz + h) * Lz + l) << 6) + dd] = v;
            }
        }
    }
}

// ctx[b, l, h*64+d] = sum_m attn[z][l][m] * v[z][m][d]   (z = b*H + h)
__global__ __launch_bounds__(256) void av_kernel(
    const float* __restrict__ attn, const float* __restrict__ v,
    float* __restrict__ ctx)
{
    __shared__ float As[TK][TM + 1];
    __shared__ float Vs[TK][HDz + 1];

    const int z = blockIdx.z;                  // 0..63
    const float* Ab = attn + (long long)z * Lz * Lz;
    const float* Vb = v    + (long long)z * Lz * HDz;
    const int bm = blockIdx.y * TM;
    const int tid = threadIdx.x;
    const int tx = tid & 15;
    const int ty = tid >> 4;

    float acc[4][4] = {};

    for (int k0 = 0; k0 < Lz; k0 += TK) {
        #pragma unroll
        for (int i = 0; i < 8; i++) {
            int idx = tid + i * 256;
            int r  = idx >> 5;
            int kk = idx & 31;
            As[kk][r] = Ab[(long long)(bm + r) * Lz + k0 + kk];
        }
        #pragma unroll
        for (int i = 0; i < 8; i++) {
            int idx = tid + i * 256;          // 2048 = 32*64
            int kk = idx >> 6;
            int dd = idx & 63;
            Vs[kk][dd] = Vb[(long long)(k0 + kk) * HDz + dd];
        }
        __syncthreads();
        #pragma unroll
        for (int kk = 0; kk < TK; kk++) {
            float a[4], w[4];
            #pragma unroll
            for (int i = 0; i < 4; i++) a[i] = As[kk][ty * 4 + i];
            #pragma unroll
            for (int j = 0; j < 4; j++) w[j] = Vs[kk][tx * 4 + j];
            #pragma unroll
            for (int i = 0; i < 4; i++)
                #pragma unroll
                for (int j = 0; j < 4; j++)
                    acc[i][j] = fmaf(a[i], w[j], acc[i][j]);
        }
        __syncthreads();
    }

    const int b = z >> 4, h = z & 15;
    #pragma unroll
    for (int i = 0; i < 4; i++) {
        int l = bm + ty * 4 + i;
        #pragma unroll
        for (int j = 0; j < 4; j++) {
            int dd = tx * 4 + j;
            ctx[((long long)b * Lz + l) * Dz + h * HDz + dd] = acc[i][j];
        }
    }
}

// In-place softmax over last dim (1024) — one block per row, 4 elems/thread.
__global__ __launch_bounds__(256) void softmax_kernel(float* __restrict__ attn)
{
    const long long row = blockIdx.x;
    float4* p = reinterpret_cast<float4*>(attn + row * Lz);
    const int tid = threadIdx.x;
    __shared__ float red[8];

    float4 v = p[tid];
    float m = fmaxf(fmaxf(v.x, v.y), fmaxf(v.z, v.w));
    #pragma unroll
    for (int o = 16; o > 0; o >>= 1) m = fmaxf(m, __shfl_xor_sync(0xFFFFFFFFu, m, o));
    if ((tid & 31) == 0) red[tid >> 5] = m;
    __syncthreads();
    m = red[0];
    #pragma unroll
    for (int i = 1; i < 8; i++) m = fmaxf(m, red[i]);
    __syncthreads();

    v.x = expf(v.x - m); v.y = expf(v.y - m);
    v.z = expf(v.z - m); v.w = expf(v.w - m);
    float s = v.x + v.y + v.z + v.w;
    #pragma unroll
    for (int o = 16; o > 0; o >>= 1) s += __shfl_xor_sync(0xFFFFFFFFu, s, o);
    if ((tid & 31) == 0) red[tid >> 5] = s;
    __syncthreads();
    s = red[0];
    #pragma unroll
    for (int i = 1; i < 8; i++) s += red[i];

    float inv = 1.0f / s;
    v.x *= inv; v.y *= inv; v.z *= inv; v.w *= inv;
    p[tid] = v;
}

// bias[m] = sum_i strength[i] * sin(m*(i+1)*pi/L) * sigmoid(field[i][m])
__global__ void bias_kernel(const float* __restrict__ field,
                            const float* __restrict__ strength,
                            float* __restrict__ bias)
{
    int m = blockIdx.x * blockDim.x + threadIdx.x;
    if (m < Lz) {
        const float pi = 3.14159265358979323846f;
        float acc = 0.0f;
        #pragma unroll
        for (int i = 0; i < ORDERz; i++) {
            float sig = 1.0f / (1.0f + expf(-field[i * Lz + m]));
            acc += strength[i] * sinf((float)m * (float)(i + 1) * pi / (float)Lz) * sig;
        }
        bias[m] = acc;
    }
}

__global__ void energy_kernel(const float* __restrict__ s, float* __restrict__ e)
{
    e[0] = (s[0] * s[0] + s[1] * s[1] + s[2] * s[2]) * (1.0f / 3.0f);
}

extern "C" void kernel_launch(void* const* d_in, const int* in_sizes, int n_in,
                              void* d_out, int out_size)
{
    const float* x  = (const float*)d_in[0];
    const float* Wq = (const float*)d_in[1];
    const float* bq = (const float*)d_in[2];
    const float* Wk = (const float*)d_in[3];
    const float* bk = (const float*)d_in[4];
    const float* Wv = (const float*)d_in[5];
    const float* bv = (const float*)d_in[6];
    const float* Wo = (const float*)d_in[7];
    const float* bo = (const float*)d_in[8];
    const float* tf = (const float*)d_in[9];
    const float* ts = (const float*)d_in[10];

    float* out    = (float*)d_out;
    float* attn   = out + (long long)Bz * Lz * Dz;                        // 4,194,304
    float* energy = attn + (long long)Bz * Hz * Lz * Lz;                  // +67,108,864

    float *gq, *gk, *gv, *gctx, *gbias;
    cudaGetSymbolAddress((void**)&gq,    g_q);
    cudaGetSymbolAddress((void**)&gk,    g_k);
    cudaGetSymbolAddress((void**)&gv,    g_v);
    cudaGetSymbolAddress((void**)&gctx,  g_ctx);
    cudaGetSymbolAddress((void**)&gbias, g_bias);

    // torsion bias + energy (tiny)
    bias_kernel<<<4, 256>>>(tf, ts, gbias);
    energy_kernel<<<1, 1>>>(ts, energy);

    // QKV projections: (4096x1024) @ (1024x1024)^T -> head layout
    dim3 gproj(Dz / TN, Mz / TM, 1);
    gemm_nt<1><<<gproj, 256>>>(x, Wq, bq, gq, Mz, Dz, Dz, 1.0f, 0, 0, 0);
    gemm_nt<1><<<gproj, 256>>>(x, Wk, bk, gk, Mz, Dz, Dz, 1.0f, 0, 0, 0);
    gemm_nt<1><<<gproj, 256>>>(x, Wv, bv, gv, Mz, Dz, Dz, 1.0f, 0, 0, 0);

    // Scores: per (b,h): (1024x64)@(1024x64)^T / 8 + bias[n], into attn
    dim3 gsc(Lz / TN, Lz / TM, Bz * Hz);
    gemm_nt<0><<<gsc, 256>>>(gq, gk, gbias, attn, Lz, Lz, HDz, 0.125f,
                             (long long)Lz * HDz, (long long)Lz * HDz,
                             (long long)Lz * Lz);

    // Softmax rows (in place on attn)
    softmax_kernel<<<Bz * Hz * Lz, 256>>>(attn);

    // ctx = attn @ V
    dim3 gav(1, Lz / TM, Bz * Hz);
    av_kernel<<<gav, 256>>>(attn, gv, gctx);

    // out = ctx @ Wo^T + bo
    gemm_nt<0><<<gproj, 256>>>(gctx, Wo, bo, out, Mz, Dz, Dz, 1.0f, 0, 0, 0);
}

// round 2
// speedup vs baseline: 1.8449x; 1.8449x over previous
#include <cuda_runtime.h>
#include <math.h>

#define Bz   4
#define Lz   1024
#define Dz   1024
#define Hz   16
#define HDz  64
#define Mz   (Bz*Lz)          // 4096
#define ORDERz 3

// Scratch (allocation-free rule: __device__ globals)
__device__ __align__(16) float g_q[Mz*Dz];     // (B,H,L,hd)
__device__ __align__(16) float g_k[Mz*Dz];     // (B,H,L,hd)
__device__ __align__(16) float g_v[Mz*Dz];     // (B,H,L,hd)
__device__ __align__(16) float g_ctx[Mz*Dz];   // (B,L,D)
__device__ __align__(16) float g_bias[Lz];

typedef unsigned long long u64t;

__device__ __forceinline__ void fma2(u64t& d, u64t a, u64t b) {
    asm("fma.rn.f32x2 %0, %1, %2, %0;" : "+l"(d) : "l"(a), "l"(b));
}
__device__ __forceinline__ u64t pack2(float x, float y) {
    u64t r; asm("mov.b64 %0, {%1, %2};" : "=l"(r) : "f"(x), "f"(y)); return r;
}
__device__ __forceinline__ float2 unpack2(u64t v) {
    float2 r; asm("mov.b64 {%0, %1}, %2;" : "=f"(r.x), "=f"(r.y) : "l"(v)); return r;
}

#define TM 128
#define TN 128
#define TK 16
#define PAD 4
#define LDA (TM + PAD)   // 132 floats per smem row (528B, 16B-aligned rows)

// C[z] = scale * A[z] @ W[z]^T + bias[n]
// A: M x K row-major, W: N x K row-major, batched via blockIdx.z.
// LAYOUT 0: C row-major M x N. LAYOUT 1: head layout (B,H,L,hd).
template<int LAYOUT>
__global__ __launch_bounds__(256) void gemm_nt(
    const float* __restrict__ A, const float* __restrict__ W,
    const float* __restrict__ bias, float* __restrict__ C,
    int K, int N, float scale,
    long long strideA, long long strideW, long long strideC)
{
    __shared__ float As[2][TK][LDA];
    __shared__ float Ws[2][TK][LDA];

    const int z = blockIdx.z;
    A += (long long)z * strideA;
    W += (long long)z * strideW;
    C += (long long)z * strideC;

    const int bm = blockIdx.y * TM;
    const int bn = blockIdx.x * TN;
    const int tid = threadIdx.x;
    const int tx  = tid & 15;      // column group
    const int ty  = tid >> 4;      // row group

    // global load coords: 2 float4 per matrix per thread
    const int lrow = tid >> 2;         // 0..63 (and +64)
    const int lc4  = (tid & 3) * 4;    // k offset 0,4,8,12

    const float* Aptr = A + (long long)(bm + lrow) * K + lc4;
    const float* Wptr = W + (long long)(bn + lrow) * K + lc4;
    const long long half = (long long)64 * K;

    u64t acc[2][4][2][2];   // [mquad][row][nquad][pair]
    #pragma unroll
    for (int a = 0; a < 2; a++)
        #pragma unroll
        for (int b = 0; b < 4; b++)
            #pragma unroll
            for (int c = 0; c < 2; c++)
                { acc[a][b][c][0] = 0ULL; acc[a][b][c][1] = 0ULL; }

    const int ntiles = K / TK;

    float4 pa0 = *(const float4*)(Aptr);
    float4 pa1 = *(const float4*)(Aptr + half);
    float4 pw0 = *(const float4*)(Wptr);
    float4 pw1 = *(const float4*)(Wptr + half);

    // stage tile 0
    {
        float va[4] = {pa0.x, pa0.y, pa0.z, pa0.w};
        float vb[4] = {pa1.x, pa1.y, pa1.z, pa1.w};
        float wa[4] = {pw0.x, pw0.y, pw0.z, pw0.w};
        float wb[4] = {pw1.x, pw1.y, pw1.z, pw1.w};
        #pragma unroll
        for (int j = 0; j < 4; j++) {
            As[0][lc4 + j][lrow]      = va[j];
            As[0][lc4 + j][lrow + 64] = vb[j];
            Ws[0][lc4 + j][lrow]      = wa[j];
            Ws[0][lc4 + j][lrow + 64] = wb[j];
        }
    }
    __syncthreads();

    for (int t = 0; t < ntiles; t++) {
        const int cur = t & 1;
        if (t + 1 < ntiles) {
            const float* Ap = Aptr + (long long)(t + 1) * TK;
            const float* Wp = Wptr + (long long)(t + 1) * TK;
            pa0 = *(const float4*)(Ap);
            pa1 = *(const float4*)(Ap + half);
            pw0 = *(const float4*)(Wp);
            pw1 = *(const float4*)(Wp + half);
        }

        #pragma unroll
        for (int kk = 0; kk < TK; kk++) {
            float4 a0 = *(const float4*)&As[cur][kk][ty * 4];
            float4 a1 = *(const float4*)&As[cur][kk][64 + ty * 4];
            ulonglong2 w0 = *(const ulonglong2*)&Ws[cur][kk][tx * 4];
            ulonglong2 w1 = *(const ulonglong2*)&Ws[cur][kk][64 + tx * 4];

            float am[2][4] = {{a0.x, a0.y, a0.z, a0.w}, {a1.x, a1.y, a1.z, a1.w}};
            #pragma unroll
            for (int mi = 0; mi < 2; mi++)
                #pragma unroll
                for (int i = 0; i < 4; i++) {
                    u64t aa = pack2(am[mi][i], am[mi][i]);
                    fma2(acc[mi][i][0][0], aa, w0.x);
                    fma2(acc[mi][i][0][1], aa, w0.y);
                    fma2(acc[mi][i][1][0], aa, w1.x);
                    fma2(acc[mi][i][1][1], aa, w1.y);
                }
        }

        if (t + 1 < ntiles) {
            const int nxt = cur ^ 1;
            float va[4] = {pa0.x, pa0.y, pa0.z, pa0.w};
            float vb[4] = {pa1.x, pa1.y, pa1.z, pa1.w};
            float wa[4] = {pw0.x, pw0.y, pw0.z, pw0.w};
            float wb[4] = {pw1.x, pw1.y, pw1.z, pw1.w};
            #pragma unroll
            for (int j = 0; j < 4; j++) {
                As[nxt][lc4 + j][lrow]      = va[j];
                As[nxt][lc4 + j][lrow + 64] = vb[j];
                Ws[nxt][lc4 + j][lrow]      = wa[j];
                Ws[nxt][lc4 + j][lrow + 64] = wb[j];
            }
            __syncthreads();
        }
    }

    // epilogue
    #pragma unroll
    for (int mi = 0; mi < 2; mi++) {
        #pragma unroll
        for (int i = 0; i < 4; i++) {
            const int m = bm + mi * 64 + ty * 4 + i;
            #pragma unroll
            for (int nj = 0; nj < 2; nj++) {
                const int n0 = bn + nj * 64 + tx * 4;
                float2 p0 = unpack2(acc[mi][i][nj][0]);
                float2 p1 = unpack2(acc[mi][i][nj][1]);
                float4 v;
                v.x = p0.x * scale + bias[n0 + 0];
                v.y = p0.y * scale + bias[n0 + 1];
                v.z = p1.x * scale + bias[n0 + 2];
                v.w = p1.y * scale + bias[n0 + 3];
                if (LAYOUT == 0) {
                    *(float4*)&C[(long long)m * N + n0] = v;
                } else {
                    int b = m >> 10, l = m & 1023;
                    int h = n0 >> 6, dd = n0 & 63;
                    *(float4*)&C[(((long long)(b * Hz + h) * Lz + l) << 6) + dd] = v;
                }
            }
        }
    }
}

// ctx[b, l, h*64+d] = sum_m attn[z][l][m] * v[z][m][d]   (z = b*H + h)
// TM=128, TN=64, TK=16, 8x4 micro per thread.
__global__ __launch_bounds__(256) void av_kernel(
    const float* __restrict__ attn, const float* __restrict__ v,
    float* __restrict__ ctx)
{
    __shared__ float As[2][TK][LDA];
    __shared__ float Vs[2][TK][HDz];

    const int z = blockIdx.z;
    const float* Ab = attn + (long long)z * Lz * Lz;
    const float* Vb = v    + (long long)z * Lz * HDz;
    const int bm = blockIdx.y * TM;
    const int tid = threadIdx.x;
    const int tx = tid & 15;
    const int ty = tid >> 4;

    const int lrow = tid >> 2;
    const int lc4  = (tid & 3) * 4;
    const float* Aptr = Ab + (long long)(bm + lrow) * Lz + lc4;
    const long long half = (long long)64 * Lz;

    const int vrow = tid >> 4;            // 0..15
    const int vc4  = (tid & 15) * 4;      // 0..60
    const float* Vptr = Vb + (long long)vrow * HDz + vc4;

    u64t acc[2][4][2];
    #pragma unroll
    for (int a = 0; a < 2; a++)
        #pragma unroll
        for (int b = 0; b < 4; b++)
            { acc[a][b][0] = 0ULL; acc[a][b][1] = 0ULL; }

    const int ntiles = Lz / TK;

    float4 pa0 = *(const float4*)(Aptr);
    float4 pa1 = *(const float4*)(Aptr + half);
    float4 pv  = *(const float4*)(Vptr);
    {
        float va[4] = {pa0.x, pa0.y, pa0.z, pa0.w};
        float vb2[4] = {pa1.x, pa1.y, pa1.z, pa1.w};
        #pragma unroll
        for (int j = 0; j < 4; j++) {
            As[0][lc4 + j][lrow]      = va[j];
            As[0][lc4 + j][lrow + 64] = vb2[j];
        }
        *(float4*)&Vs[0][vrow][vc4] = pv;
    }
    __syncthreads();

    for (int t = 0; t < ntiles; t++) {
        const int cur = t & 1;
        if (t + 1 < ntiles) {
            const float* Ap = Aptr + (long long)(t + 1) * TK;
            pa0 = *(const float4*)(Ap);
            pa1 = *(const float4*)(Ap + half);
            pv  = *(const float4*)(Vptr + (long long)(t + 1) * TK * HDz);
        }

        #pragma unroll
        for (int kk = 0; kk < TK; kk++) {
            float4 a0 = *(const float4*)&As[cur][kk][ty * 4];
            float4 a1 = *(const float4*)&As[cur][kk][64 + ty * 4];
            ulonglong2 w0 = *(const ulonglong2*)&Vs[cur][kk][tx * 4];

            float am[2][4] = {{a0.x, a0.y, a0.z, a0.w}, {a1.x, a1.y, a1.z, a1.w}};
            #pragma unroll
            for (int mi = 0; mi < 2; mi++)
                #pragma unroll
                for (int i = 0; i < 4; i++) {
                    u64t aa = pack2(am[mi][i], am[mi][i]);
                    fma2(acc[mi][i][0], aa, w0.x);
                    fma2(acc[mi][i][1], aa, w0.y);
                }
        }

        if (t + 1 < ntiles) {
            const int nxt = cur ^ 1;
            float va[4] = {pa0.x, pa0.y, pa0.z, pa0.w};
            float vb2[4] = {pa1.x, pa1.y, pa1.z, pa1.w};
            #pragma unroll
            for (int j = 0; j < 4; j++) {
                As[nxt][lc4 + j][lrow]      = va[j];
                As[nxt][lc4 + j][lrow + 64] = vb2[j];
            }
            *(float4*)&Vs[nxt][vrow][vc4] = pv;
            __syncthreads();
        }
    }

    const int b = z >> 4, h = z & 15;
    #pragma unroll
    for (int mi = 0; mi < 2; mi++)
        #pragma unroll
        for (int i = 0; i < 4; i++) {
            const int l = bm + mi * 64 + ty * 4 + i;
            float2 p0 = unpack2(acc[mi][i][0]);
            float2 p1 = unpack2(acc[mi][i][1]);
            float4 o; o.x = p0.x; o.y = p0.y; o.z = p1.x; o.w = p1.y;
            *(float4*)&ctx[((long long)b * Lz + l) * Dz + h * HDz + tx * 4] = o;
        }
}

// In-place softmax over last dim (1024) — one block per row, 4 elems/thread.
__global__ __launch_bounds__(256) void softmax_kernel(float* __restrict__ attn)
{
    const long long row = blockIdx.x;
    float4* p = reinterpret_cast<float4*>(attn + row * Lz);
    const int tid = threadIdx.x;
    __shared__ float red[8];

    float4 v = p[tid];
    float m = fmaxf(fmaxf(v.x, v.y), fmaxf(v.z, v.w));
    #pragma unroll
    for (int o = 16; o > 0; o >>= 1) m = fmaxf(m, __shfl_xor_sync(0xFFFFFFFFu, m, o));
    if ((tid & 31) == 0) red[tid >> 5] = m;
    __syncthreads();
    m = red[0];
    #pragma unroll
    for (int i = 1; i < 8; i++) m = fmaxf(m, red[i]);
    __syncthreads();

    v.x = expf(v.x - m); v.y = expf(v.y - m);
    v.z = expf(v.z - m); v.w = expf(v.w - m);
    float s = v.x + v.y + v.z + v.w;
    #pragma unroll
    for (int o = 16; o > 0; o >>= 1) s += __shfl_xor_sync(0xFFFFFFFFu, s, o);
    if ((tid & 31) == 0) red[tid >> 5] = s;
    __syncthreads();
    s = red[0];
    #pragma unroll
    for (int i = 1; i < 8; i++) s += red[i];

    float inv = 1.0f / s;
    v.x *= inv; v.y *= inv; v.z *= inv; v.w *= inv;
    p[tid] = v;
}

__global__ void bias_kernel(const float* __restrict__ field,
                            const float* __restrict__ strength,
                            float* __restrict__ bias)
{
    int m = blockIdx.x * blockDim.x + threadIdx.x;
    if (m < Lz) {
        const float pi = 3.14159265358979323846f;
        float acc = 0.0f;
        #pragma unroll
        for (int i = 0; i < ORDERz; i++) {
            float sig = 1.0f / (1.0f + expf(-field[i * Lz + m]));
            acc += strength[i] * sinf((float)m * (float)(i + 1) * pi / (float)Lz) * sig;
        }
        bias[m] = acc;
    }
}

__global__ void energy_kernel(const float* __restrict__ s, float* __restrict__ e)
{
    e[0] = (s[0] * s[0] + s[1] * s[1] + s[2] * s[2]) * (1.0f / 3.0f);
}

extern "C" void kernel_launch(void* const* d_in, const int* in_sizes, int n_in,
                              void* d_out, int out_size)
{
    const float* x  = (const float*)d_in[0];
    const float* Wq = (const float*)d_in[1];
    const float* bq = (const float*)d_in[2];
    const float* Wk = (const float*)d_in[3];
    const float* bk = (const float*)d_in[4];
    const float* Wv = (const float*)d_in[5];
    const float* bv = (const float*)d_in[6];
    const float* Wo = (const float*)d_in[7];
    const float* bo = (const float*)d_in[8];
    const float* tf = (const float*)d_in[9];
    const float* ts = (const float*)d_in[10];

    float* out    = (float*)d_out;
    float* attn   = out + (long long)Bz * Lz * Dz;
    float* energy = attn + (long long)Bz * Hz * Lz * Lz;

    float *gq, *gk, *gv, *gctx, *gbias;
    cudaGetSymbolAddress((void**)&gq,    g_q);
    cudaGetSymbolAddress((void**)&gk,    g_k);
    cudaGetSymbolAddress((void**)&gv,    g_v);
    cudaGetSymbolAddress((void**)&gctx,  g_ctx);
    cudaGetSymbolAddress((void**)&gbias, g_bias);

    bias_kernel<<<4, 256>>>(tf, ts, gbias);
    energy_kernel<<<1, 1>>>(ts, energy);

    // QKV projections: (4096x1024) @ (1024x1024)^T -> head layout
    dim3 gproj(Dz / TN, Mz / TM, 1);
    gemm_nt<1><<<gproj, 256>>>(x, Wq, bq, gq, Dz, Dz, 1.0f, 0, 0, 0);
    gemm_nt<1><<<gproj, 256>>>(x, Wk, bk, gk, Dz, Dz, 1.0f, 0, 0, 0);
    gemm_nt<1><<<gproj, 256>>>(x, Wv, bv, gv, Dz, Dz, 1.0f, 0, 0, 0);

    // Scores: per (b,h): (1024x64)@(1024x64)^T / 8 + bias[n]
    dim3 gsc(Lz / TN, Lz / TM, Bz * Hz);
    gemm_nt<0><<<gsc, 256>>>(gq, gk, gbias, attn, HDz, Lz, 0.125f,
                             (long long)Lz * HDz, (long long)Lz * HDz,
                             (long long)Lz * Lz);

    softmax_kernel<<<Bz * Hz * Lz, 256>>>(attn);

    // ctx = attn @ V
    dim3 gav(1, Lz / TM, Bz * Hz);
    av_kernel<<<gav, 256>>>(attn, gv, gctx);

    // out = ctx @ Wo^T + bo
    gemm_nt<0><<<gproj, 256>>>(gctx, Wo, bo, out, Dz, Dz, 1.0f, 0, 0, 0);
}

// round 4
// speedup vs baseline: 2.4212x; 1.3124x over previous
#include <cuda_runtime.h>
#include <cuda_bf16.h>
#include <math.h>
#include <stdint.h>

#define Bz   4
#define Lz   1024
#define Dz   1024
#define Hz   16
#define HDz  64
#define Mz   (Bz*Lz)          // 4096
#define ORDERz 3

// ---------------- scratch (__device__ globals: allocation-free rule) ----------
__device__ __align__(16) float g_q[Mz*Dz];     // (B,H,L,hd)
__device__ __align__(16) float g_k[Mz*Dz];     // (B,H,L,hd)
__device__ __align__(16) float g_v[Mz*Dz];     // (B,H,L,hd)
__device__ __align__(16) float g_ctx[Mz*Dz];   // (B,L,D)
__device__ __align__(16) float g_bias[Lz];

__device__ __align__(16) __nv_bfloat16 g_xh[Mz*Dz], g_xl[Mz*Dz];
__device__ __align__(16) __nv_bfloat16 g_wh[4][Dz*Dz], g_wl[4][Dz*Dz]; // q,k,v,o
__device__ __align__(16) __nv_bfloat16 g_ch[Mz*Dz], g_cl[Mz*Dz];

// ---------------- PTX helpers ----------------------------------------------------
__device__ __forceinline__ uint32_t smem_u32(const void* p) {
    uint32_t a;
    asm("{ .reg .u64 t; cvta.to.shared.u64 t, %1; cvt.u32.u64 %0, t; }" : "=r"(a) : "l"(p));
    return a;
}
__device__ __forceinline__ void cpasync16(uint32_t s, const void* g) {
    asm volatile("cp.async.cg.shared.global [%0], [%1], 16;" :: "r"(s), "l"(g));
}
#define CP_COMMIT()  asm volatile("cp.async.commit_group;" ::: "memory")
#define CP_WAIT1()   asm volatile("cp.async.wait_group 1;" ::: "memory")
#define CP_WAIT0()   asm volatile("cp.async.wait_group 0;" ::: "memory")

__device__ __forceinline__ void hmma(float* d, const uint32_t* a, const uint32_t* b) {
    asm volatile(
        "mma.sync.aligned.m16n8k16.row.col.f32.bf16.bf16.f32 "
        "{%0,%1,%2,%3}, {%4,%5,%6,%7}, {%8,%9}, {%0,%1,%2,%3};"
        : "+f"(d[0]), "+f"(d[1]), "+f"(d[2]), "+f"(d[3])
        : "r"(a[0]), "r"(a[1]), "r"(a[2]), "r"(a[3]), "r"(b[0]), "r"(b[1]));
}

// ---------------- HMMA split-bf16 GEMM --------------------------------------------
// C[m][n] = scale * sum_k A[m][k]*B[n][k] + bias[n]
// A: M x K (K-major bf16 hi/lo), B: N x K (K-major bf16 hi/lo).
// CTA tile 128x128, K-chunk 32, double-buffered cp.async.
// LAYOUT 0: C row-major M x N. LAYOUT 1: head layout (B,H,L,hd).
#define KC 32
#define ROWB 80                          // 32 bf16 + 8 pad = 80 bytes per smem row
#define MAT_BYTES (128 * ROWB)           // 10240
#define STAGE_BYTES (4 * MAT_BYTES)      // 40960
#define HSMEM (2 * STAGE_BYTES)          // 81920

template<int LAYOUT>
__global__ __launch_bounds__(256) void hmma_gemm(
    const __nv_bfloat16* __restrict__ Ah, const __nv_bfloat16* __restrict__ Al,
    const __nv_bfloat16* __restrict__ Bh, const __nv_bfloat16* __restrict__ Bl,
    const float* __restrict__ bias, float* __restrict__ C,
    int K, int N, float scale)
{
    extern __shared__ char sm[];
    const uint32_t sbase = smem_u32(sm);

    const int tid  = threadIdx.x;
    const int warp = tid >> 5;
    const int lane = tid & 31;
    const int g = lane >> 2;         // group 0..7
    const int t = lane & 3;          // thread-in-group
    const int wm = (warp >> 2) * 64; // warp m-offset within CTA tile
    const int wn = (warp & 3) * 32;  // warp n-offset

    const int bm = blockIdx.y * 128;
    const int bn = blockIdx.x * 128;

    const __nv_bfloat16* tAh = Ah + (size_t)bm * K;
    const __nv_bfloat16* tAl = Al + (size_t)bm * K;
    const __nv_bfloat16* tBh = Bh + (size_t)bn * K;
    const __nv_bfloat16* tBl = Bl + (size_t)bn * K;

    // global-load geometry: 512 uint4 per matrix per chunk, 2 per thread
    const int r0 = tid >> 2;         // row for unit tid   (0..63)
    const int r1 = r0 + 64;          // row for unit tid+256
    const int sg = tid & 3;          // 16B segment within 64B row

    auto prefetch = [&](int c, int stage) {
        const uint32_t sb = sbase + stage * STAGE_BYTES;
        const size_t go0 = (size_t)r0 * K + c * KC + sg * 8;
        const size_t go1 = (size_t)r1 * K + c * KC + sg * 8;
        const uint32_t so0 = r0 * ROWB + sg * 16;
        const uint32_t so1 = r1 * ROWB + sg * 16;
        cpasync16(sb + 0 * MAT_BYTES + so0, tAh + go0);
        cpasync16(sb + 0 * MAT_BYTES + so1, tAh + go1);
        cpasync16(sb + 1 * MAT_BYTES + so0, tAl + go0);
        cpasync16(sb + 1 * MAT_BYTES + so1, tAl + go1);
        cpasync16(sb + 2 * MAT_BYTES + so0, tBh + go0);
        cpasync16(sb + 2 * MAT_BYTES + so1, tBh + go1);
        cpasync16(sb + 3 * MAT_BYTES + so0, tBl + go0);
        cpasync16(sb + 3 * MAT_BYTES + so1, tBl + go1);
    };

    float acc[4][4][4];
    #pragma unroll
    for (int i = 0; i < 4; i++)
        #pragma unroll
        for (int j = 0; j < 4; j++)
            #pragma unroll
            for (int k = 0; k < 4; k++) acc[i][j][k] = 0.0f;

    const int nch = K / KC;

    prefetch(0, 0); CP_COMMIT();
    prefetch(1, 1); CP_COMMIT();

    for (int c = 0; c < nch; c++) {
        if (c + 1 < nch) { CP_WAIT1(); } else { CP_WAIT0(); }
        __syncthreads();

        const uint32_t sb  = sbase + (c & 1) * STAGE_BYTES;
        const uint32_t sAh = sb;
        const uint32_t sAl = sb + 1 * MAT_BYTES;
        const uint32_t sBh = sb + 2 * MAT_BYTES;
        const uint32_t sBl = sb + 3 * MAT_BYTES;

        #pragma unroll
        for (int kk = 0; kk < KC; kk += 16) {
            const uint32_t cofs = (kk + 2 * t) * 2;   // byte offset of k-col pair

            // B fragments (4 n-tiles x 2 regs, hi+lo)
            uint32_t bH[4][2], bL[4][2];
            #pragma unroll
            for (int nt = 0; nt < 4; nt++) {
                const uint32_t ro = (wn + nt * 8 + g) * ROWB + cofs;
                bH[nt][0] = *(const uint32_t*)(sm + (sBh - sbase) + ro);
                bH[nt][1] = *(const uint32_t*)(sm + (sBh - sbase) + ro + 16);
                bL[nt][0] = *(const uint32_t*)(sm + (sBl - sbase) + ro);
                bL[nt][1] = *(const uint32_t*)(sm + (sBl - sbase) + ro + 16);
            }

            #pragma unroll
            for (int mt = 0; mt < 4; mt++) {
                const uint32_t ro = (wm + mt * 16 + g) * ROWB + cofs;
                uint32_t aH[4], aL[4];
                aH[0] = *(const uint32_t*)(sm + (sAh - sbase) + ro);
                aH[1] = *(const uint32_t*)(sm + (sAh - sbase) + ro + 8 * ROWB);
                aH[2] = *(const uint32_t*)(sm + (sAh - sbase) + ro + 16);
                aH[3] = *(const uint32_t*)(sm + (sAh - sbase) + ro + 8 * ROWB + 16);
                aL[0] = *(const uint32_t*)(sm + (sAl - sbase) + ro);
                aL[1] = *(const uint32_t*)(sm + (sAl - sbase) + ro + 8 * ROWB);
                aL[2] = *(const uint32_t*)(sm + (sAl - sbase) + ro + 16);
                aL[3] = *(const uint32_t*)(sm + (sAl - sbase) + ro + 8 * ROWB + 16);

                #pragma unroll
                for (int nt = 0; nt < 4; nt++) {
                    hmma(acc[mt][nt], aH, bH[nt]);
                    hmma(acc[mt][nt], aH, bL[nt]);
                    hmma(acc[mt][nt], aL, bH[nt]);
                }
            }
        }

        __syncthreads();
        if (c + 2 < nch) { prefetch(c + 2, (c & 1)); CP_COMMIT(); }
        else { CP_COMMIT(); }   // keep group count in sync for wait_group 1
    }

    // epilogue
    #pragma unroll
    for (int mt = 0; mt < 4; mt++) {
        const int m0 = bm + wm + mt * 16 + g;
        #pragma unroll
        for (int nt = 0; nt < 4; nt++) {
            const int n0 = bn + wn + nt * 8 + 2 * t;
            const float b0 = bias[n0], b1 = bias[n0 + 1];
            float2 lo = make_float2(acc[mt][nt][0] * scale + b0, acc[mt][nt][1] * scale + b1);
            float2 hi = make_float2(acc[mt][nt][2] * scale + b0, acc[mt][nt][3] * scale + b1);
            if (LAYOUT == 0) {
                *(float2*)&C[(size_t)m0 * N + n0]       = lo;
                *(float2*)&C[(size_t)(m0 + 8) * N + n0] = hi;
            } else {
                const int h = n0 >> 6, dd = n0 & 63;
                const int b = m0 >> 10, l = m0 & 1023;
                float* base = C + (((size_t)(b * Hz + h) * Lz) << 6) + dd;
                *(float2*)(base + ((size_t)l << 6))       = lo;
                *(float2*)(base + ((size_t)(l + 8) << 6)) = hi;
            }
        }
    }
}

// ---------------- fp32 -> bf16 hi/lo split ----------------------------------------
__global__ __launch_bounds__(256) void split_kernel(
    const float* __restrict__ in, __nv_bfloat16* __restrict__ hi,
    __nv_bfloat16* __restrict__ lo, int n4)
{
    int i = blockIdx.x * blockDim.x + threadIdx.x;
    if (i < n4) {
        float4 v = ((const float4*)in)[i];
        __nv_bfloat16 h0 = __float2bfloat16(v.x);
        __nv_bfloat16 h1 = __float2bfloat16(v.y);
        __nv_bfloat16 h2 = __float2bfloat16(v.z);
        __nv_bfloat16 h3 = __float2bfloat16(v.w);
        __nv_bfloat162* H = (__nv_bfloat162*)hi;
        __nv_bfloat162* L = (__nv_bfloat162*)lo;
        H[i*2+0] = __nv_bfloat162(h0, h1);
        H[i*2+1] = __nv_bfloat162(h2, h3);
        L[i*2+0] = __nv_bfloat162(__float2bfloat16(v.x - __bfloat162float(h0)),
                                  __float2bfloat16(v.y - __bfloat162float(h1)));
        L[i*2+1] = __nv_bfloat162(__float2bfloat16(v.z - __bfloat162float(h2)),
                                  __float2bfloat16(v.w - __bfloat162float(h3)));
    }
}

// ---------------- SIMT kernels (scores / softmax / AV) ----------------------------
typedef unsigned long long u64t;
__device__ __forceinline__ void fma2(u64t& d, u64t a, u64t b) {
    asm("fma.rn.f32x2 %0, %1, %2, %0;" : "+l"(d) : "l"(a), "l"(b));
}
__device__ __forceinline__ u64t pack2(float x, float y) {
    u64t r; asm("mov.b64 %0, {%1, %2};" : "=l"(r) : "f"(x), "f"(y)); return r;
}
__device__ __forceinline__ float2 unpack2(u64t v) {
    float2 r; asm("mov.b64 {%0, %1}, %2;" : "=f"(r.x), "=f"(r.y) : "l"(v)); return r;
}

#define TM 128
#define TN 128
#define TK 16
#define PAD 4
#define LDA (TM + PAD)

__global__ __launch_bounds__(256) void gemm_nt_simt(
    const float* __restrict__ A, const float* __restrict__ W,
    const float* __restrict__ bias, float* __restrict__ C,
    int K, int N, float scale,
    long long strideA, long long strideW, long long strideC)
{
    __shared__ float As[2][TK][LDA];
    __shared__ float Ws[2][TK][LDA];

    const int z = blockIdx.z;
    A += (long long)z * strideA;
    W += (long long)z * strideW;
    C += (long long)z * strideC;

    const int bm = blockIdx.y * TM;
    const int bn = blockIdx.x * TN;
    const int tid = threadIdx.x;
    const int tx  = tid & 15;
    const int ty  = tid >> 4;

    const int lrow = tid >> 2;
    const int lc4  = (tid & 3) * 4;

    const float* Aptr = A + (long long)(bm + lrow) * K + lc4;
    const float* Wptr = W + (long long)(bn + lrow) * K + lc4;
    const long long half = (long long)64 * K;

    u64t acc[2][4][2][2];
    #pragma unroll
    for (int a = 0; a < 2; a++)
        #pragma unroll
        for (int b = 0; b < 4; b++)
            #pragma unroll
            for (int c = 0; c < 2; c++)
                { acc[a][b][c][0] = 0ULL; acc[a][b][c][1] = 0ULL; }

    const int ntiles = K / TK;

    float4 pa0 = *(const float4*)(Aptr);
    float4 pa1 = *(const float4*)(Aptr + half);
    float4 pw0 = *(const float4*)(Wptr);
    float4 pw1 = *(const float4*)(Wptr + half);

    {
        float va[4] = {pa0.x, pa0.y, pa0.z, pa0.w};
        float vb[4] = {pa1.x, pa1.y, pa1.z, pa1.w};
        float wa[4] = {pw0.x, pw0.y, pw0.z, pw0.w};
        float wb[4] = {pw1.x, pw1.y, pw1.z, pw1.w};
        #pragma unroll
        for (int j = 0; j < 4; j++) {
            As[0][lc4 + j][lrow]      = va[j];
            As[0][lc4 + j][lrow + 64] = vb[j];
            Ws[0][lc4 + j][lrow]      = wa[j];
            Ws[0][lc4 + j][lrow + 64] = wb[j];
        }
    }
    __syncthreads();

    for (int t = 0; t < ntiles; t++) {
        const int cur = t & 1;
        if (t + 1 < ntiles) {
            const float* Ap = Aptr + (long long)(t + 1) * TK;
            const float* Wp = Wptr + (long long)(t + 1) * TK;
            pa0 = *(const float4*)(Ap);
            pa1 = *(const float4*)(Ap + half);
            pw0 = *(const float4*)(Wp);
            pw1 = *(const float4*)(Wp + half);
        }

        #pragma unroll
        for (int kk = 0; kk < TK; kk++) {
            float4 a0 = *(const float4*)&As[cur][kk][ty * 4];
            float4 a1 = *(const float4*)&As[cur][kk][64 + ty * 4];
            ulonglong2 w0 = *(const ulonglong2*)&Ws[cur][kk][tx * 4];
            ulonglong2 w1 = *(const ulonglong2*)&Ws[cur][kk][64 + tx * 4];

            float am[2][4] = {{a0.x, a0.y, a0.z, a0.w}, {a1.x, a1.y, a1.z, a1.w}};
            #pragma unroll
            for (int mi = 0; mi < 2; mi++)
                #pragma unroll
                for (int i = 0; i < 4; i++) {
                    u64t aa = pack2(am[mi][i], am[mi][i]);
                    fma2(acc[mi][i][0][0], aa, w0.x);
                    fma2(acc[mi][i][0][1], aa, w0.y);
                    fma2(acc[mi][i][1][0], aa, w1.x);
                    fma2(acc[mi][i][1][1], aa, w1.y);
                }
        }

        if (t + 1 < ntiles) {
            const int nxt = cur ^ 1;
            float va[4] = {pa0.x, pa0.y, pa0.z, pa0.w};
            float vb[4] = {pa1.x, pa1.y, pa1.z, pa1.w};
            float wa[4] = {pw0.x, pw0.y, pw0.z, pw0.w};
            float wb[4] = {pw1.x, pw1.y, pw1.z, pw1.w};
            #pragma unroll
            for (int j = 0; j < 4; j++) {
                As[nxt][lc4 + j][lrow]      = va[j];
                As[nxt][lc4 + j][lrow + 64] = vb[j];
                Ws[nxt][lc4 + j][lrow]      = wa[j];
                Ws[nxt][lc4 + j][lrow + 64] = wb[j];
            }
            __syncthreads();
        }
    }

    #pragma unroll
    for (int mi = 0; mi < 2; mi++) {
        #pragma unroll
        for (int i = 0; i < 4; i++) {
            const int m = bm + mi * 64 + ty * 4 + i;
            #pragma unroll
            for (int nj = 0; nj < 2; nj++) {
                const int n0 = bn + nj * 64 + tx * 4;
                float2 p0 = unpack2(acc[mi][i][nj][0]);
                float2 p1 = unpack2(acc[mi][i][nj][1]);
                float4 v;
                v.x = p0.x * scale + bias[n0 + 0];
                v.y = p0.y * scale + bias[n0 + 1];
                v.z = p1.x * scale + bias[n0 + 2];
                v.w = p1.y * scale + bias[n0 + 3];
                *(float4*)&C[(long long)m * N + n0] = v;
            }
        }
    }
}

__global__ __launch_bounds__(256) void av_kernel(
    const float* __restrict__ attn, const float* __restrict__ v,
    float* __restrict__ ctx)
{
    __shared__ float As[2][TK][LDA];
    __shared__ float Vs[2][TK][HDz];

    const int z = blockIdx.z;
    const float* Ab = attn + (long long)z * Lz * Lz;
    const float* Vb = v    + (long long)z * Lz * HDz;
    const int bm = blockIdx.y * TM;
    const int tid = threadIdx.x;
    const int tx = tid & 15;
    const int ty = tid >> 4;

    const int lrow = tid >> 2;
    const int lc4  = (tid & 3) * 4;
    const float* Aptr = Ab + (long long)(bm + lrow) * Lz + lc4;
    const long long half = (long long)64 * Lz;

    const int vrow = tid >> 4;
    const int vc4  = (tid & 15) * 4;
    const float* Vptr = Vb + (long long)vrow * HDz + vc4;

    u64t acc[2][4][2];
    #pragma unroll
    for (int a = 0; a < 2; a++)
        #pragma unroll
        for (int b = 0; b < 4; b++)
            { acc[a][b][0] = 0ULL; acc[a][b][1] = 0ULL; }

    const int ntiles = Lz / TK;

    float4 pa0 = *(const float4*)(Aptr);
    float4 pa1 = *(const float4*)(Aptr + half);
    float4 pv  = *(const float4*)(Vptr);
    {
        float va[4] = {pa0.x, pa0.y, pa0.z, pa0.w};
        float vb2[4] = {pa1.x, pa1.y, pa1.z, pa1.w};
        #pragma unroll
        for (int j = 0; j < 4; j++) {
            As[0][lc4 + j][lrow]      = va[j];
            As[0][lc4 + j][lrow + 64] = vb2[j];
        }
        *(float4*)&Vs[0][vrow][vc4] = pv;
    }
    __syncthreads();

    for (int t = 0; t < ntiles; t++) {
        const int cur = t & 1;
        if (t + 1 < ntiles) {
            const float* Ap = Aptr + (long long)(t + 1) * TK;
            pa0 = *(const float4*)(Ap);
            pa1 = *(const float4*)(Ap + half);
            pv  = *(const float4*)(Vptr + (long long)(t + 1) * TK * HDz);
        }

        #pragma unroll
        for (int kk = 0; kk < TK; kk++) {
            float4 a0 = *(const float4*)&As[cur][kk][ty * 4];
            float4 a1 = *(const float4*)&As[cur][kk][64 + ty * 4];
            ulonglong2 w0 = *(const ulonglong2*)&Vs[cur][kk][tx * 4];

            float am[2][4] = {{a0.x, a0.y, a0.z, a0.w}, {a1.x, a1.y, a1.z, a1.w}};
            #pragma unroll
            for (int mi = 0; mi < 2; mi++)
                #pragma unroll
                for (int i = 0; i < 4; i++) {
                    u64t aa = pack2(am[mi][i], am[mi][i]);
                    fma2(acc[mi][i][0], aa, w0.x);
                    fma2(acc[mi][i][1], aa, w0.y);
                }
        }

        if (t + 1 < ntiles) {
            const int nxt = cur ^ 1;
            float va[4] = {pa0.x, pa0.y, pa0.z, pa0.w};
            float vb2[4] = {pa1.x, pa1.y, pa1.z, pa1.w};
            #pragma unroll
            for (int j = 0; j < 4; j++) {
                As[nxt][lc4 + j][lrow]      = va[j];
                As[nxt][lc4 + j][lrow + 64] = vb2[j];
            }
            *(float4*)&Vs[nxt][vrow][vc4] = pv;
            __syncthreads();
        }
    }

    const int b = z >> 4, h = z & 15;
    #pragma unroll
    for (int mi = 0; mi < 2; mi++)
        #pragma unroll
        for (int i = 0; i < 4; i++) {
            const int l = bm + mi * 64 + ty * 4 + i;
            float2 p0 = unpack2(acc[mi][i][0]);
            float2 p1 = unpack2(acc[mi][i][1]);
            float4 o; o.x = p0.x; o.y = p0.y; o.z = p1.x; o.w = p1.y;
            *(float4*)&ctx[((long long)b * Lz + l) * Dz + h * HDz + tx * 4] = o;
        }
}

__global__ __launch_bounds__(256) void softmax_kernel(float* __restrict__ attn)
{
    const long long row = blockIdx.x;
    float4* p = reinterpret_cast<float4*>(attn + row * Lz);
    const int tid = threadIdx.x;
    __shared__ float red[8];

    float4 v = p[tid];
    float m = fmaxf(fmaxf(v.x, v.y), fmaxf(v.z, v.w));
    #pragma unroll
    for (int o = 16; o > 0; o >>= 1) m = fmaxf(m, __shfl_xor_sync(0xFFFFFFFFu, m, o));
    if ((tid & 31) == 0) red[tid >> 5] = m;
    __syncthreads();
    m = red[0];
    #pragma unroll
    for (int i = 1; i < 8; i++) m = fmaxf(m, red[i]);
    __syncthreads();

    v.x = expf(v.x - m); v.y = expf(v.y - m);
    v.z = expf(v.z - m); v.w = expf(v.w - m);
    float s = v.x + v.y + v.z + v.w;
    #pragma unroll
    for (int o = 16; o > 0; o >>= 1) s += __shfl_xor_sync(0xFFFFFFFFu, s, o);
    if ((tid & 31) == 0) red[tid >> 5] = s;
    __syncthreads();
    s = red[0];
    #pragma unroll
    for (int i = 1; i < 8; i++) s += red[i];

    float inv = 1.0f / s;
    v.x *= inv; v.y *= inv; v.z *= inv; v.w *= inv;
    p[tid] = v;
}

__global__ void bias_kernel(const float* __restrict__ field,
                            const float* __restrict__ strength,
                            float* __restrict__ bias)
{
    int m = blockIdx.x * blockDim.x + threadIdx.x;
    if (m < Lz) {
        const float pi = 3.14159265358979323846f;
        float acc = 0.0f;
        #pragma unroll
        for (int i = 0; i < ORDERz; i++) {
            float sig = 1.0f / (1.0f + expf(-field[i * Lz + m]));
            acc += strength[i] * sinf((float)m * (float)(i + 1) * pi / (float)Lz) * sig;
        }
        bias[m] = acc;
    }
}

__global__ void energy_kernel(const float* __restrict__ s, float* __restrict__ e)
{
    e[0] = (s[0] * s[0] + s[1] * s[1] + s[2] * s[2]) * (1.0f / 3.0f);
}

// ---------------- launch ------------------------------------------------------------
extern "C" void kernel_launch(void* const* d_in, const int* in_sizes, int n_in,
                              void* d_out, int out_size)
{
    const float* x  = (const float*)d_in[0];
    const float* Wq = (const float*)d_in[1];
    const float* bq = (const float*)d_in[2];
    const float* Wk = (const float*)d_in[3];
    const float* bk = (const float*)d_in[4];
    const float* Wv = (const float*)d_in[5];
    const float* bv = (const float*)d_in[6];
    const float* Wo = (const float*)d_in[7];
    const float* bo = (const float*)d_in[8];
    const float* tf = (const float*)d_in[9];
    const float* ts = (const float*)d_in[10];

    float* out    = (float*)d_out;
    float* attn   = out + (long long)Bz * Lz * Dz;
    float* energy = attn + (long long)Bz * Hz * Lz * Lz;

    float *gq, *gk, *gv, *gctx, *gbias;
    cudaGetSymbolAddress((void**)&gq,    g_q);
    cudaGetSymbolAddress((void**)&gk,    g_k);
    cudaGetSymbolAddress((void**)&gv,    g_v);
    cudaGetSymbolAddress((void**)&gctx,  g_ctx);
    cudaGetSymbolAddress((void**)&gbias, g_bias);

    __nv_bfloat16 *xh, *xl, *wh, *wl, *ch, *cl;
    cudaGetSymbolAddress((void**)&xh, g_xh);
    cudaGetSymbolAddress((void**)&xl, g_xl);
    cudaGetSymbolAddress((void**)&wh, g_wh);
    cudaGetSymbolAddress((void**)&wl, g_wl);
    cudaGetSymbolAddress((void**)&ch, g_ch);
    cudaGetSymbolAddress((void**)&cl, g_cl);

    cudaFuncSetAttribute(hmma_gemm<0>, cudaFuncAttributeMaxDynamicSharedMemorySize, HSMEM);
    cudaFuncSetAttribute(hmma_gemm<1>, cudaFuncAttributeMaxDynamicSharedMemorySize, HSMEM);

    bias_kernel<<<4, 256>>>(tf, ts, gbias);
    energy_kernel<<<1, 1>>>(ts, energy);

    // fp32 -> bf16 splits
    const size_t WN = (size_t)Dz * Dz;
    split_kernel<<<(Mz*Dz/4 + 255)/256, 256>>>(x,  xh, xl, Mz*Dz/4);
    split_kernel<<<(WN/4 + 255)/256, 256>>>(Wq, wh + 0*WN, wl + 0*WN, WN/4);
    split_kernel<<<(WN/4 + 255)/256, 256>>>(Wk, wh + 1*WN, wl + 1*WN, WN/4);
    split_kernel<<<(WN/4 + 255)/256, 256>>>(Wv, wh + 2*WN, wl + 2*WN, WN/4);
    split_kernel<<<(WN/4 + 255)/256, 256>>>(Wo, wh + 3*WN, wl + 3*WN, WN/4);

    // QKV projections on tensor cores -> fp32 head layout
    dim3 gproj(Dz / 128, Mz / 128);   // (8, 32)
    hmma_gemm<1><<<gproj, 256, HSMEM>>>(xh, xl, wh + 0*WN, wl + 0*WN, bq, gq, Dz, Dz, 1.0f);
    hmma_gemm<1><<<gproj, 256, HSMEM>>>(xh, xl, wh + 1*WN, wl + 1*WN, bk, gk, Dz, Dz, 1.0f);
    hmma_gemm<1><<<gproj, 256, HSMEM>>>(xh, xl, wh + 2*WN, wl + 2*WN, bv, gv, Dz, Dz, 1.0f);

    // scores (SIMT): per (b,h): (1024x64)@(1024x64)^T / 8 + bias[n]
    dim3 gsc(Lz / TN, Lz / TM, Bz * Hz);
    gemm_nt_simt<<<gsc, 256>>>(gq, gk, gbias, attn, HDz, Lz, 0.125f,
                               (long long)Lz * HDz, (long long)Lz * HDz,
                               (long long)Lz * Lz);

    softmax_kernel<<<Bz * Hz * Lz, 256>>>(attn);

    dim3 gav(1, Lz / TM, Bz * Hz);
    av_kernel<<<gav, 256>>>(attn, gv, gctx);

    // out = ctx @ Wo^T + bo on tensor cores
    split_kernel<<<(Mz*Dz/4 + 255)/256, 256>>>(gctx, ch, cl, Mz*Dz/4);
    hmma_gemm<0><<<gproj, 256, HSMEM>>>(ch, cl, wh + 3*WN, wl + 3*WN, bo, out, Dz, Dz, 1.0f);
}

// round 5
// speedup vs baseline: 2.7464x; 1.1343x over previous
#include <cuda_runtime.h>
#include <cuda_bf16.h>
#include <math.h>
#include <stdint.h>

#define Bz   4
#define Lz   1024
#define Dz   1024
#define Hz   16
#define HDz  64
#define Mz   (Bz*Lz)          // 4096
#define ORDERz 3
#define ZN   (Bz*Hz)          // 64

// ---------------- scratch (__device__ globals) ----------------------------------
__device__ __align__(16) float g_v[Mz*Dz];     // (B,H,L,hd) fp32
__device__ __align__(16) float g_bias[Lz];

__device__ __align__(16) __nv_bfloat16 g_xh[Mz*Dz], g_xl[Mz*Dz];
__device__ __align__(16) __nv_bfloat16 g_wh[4][Dz*Dz], g_wl[4][Dz*Dz]; // q,k,v,o
__device__ __align__(16) __nv_bfloat16 g_qh[Mz*Dz], g_ql[Mz*Dz];       // (B,H,L,hd)
__device__ __align__(16) __nv_bfloat16 g_kh[Mz*Dz], g_kl[Mz*Dz];       // (B,H,L,hd)
__device__ __align__(16) __nv_bfloat16 g_vth[Mz*Dz], g_vtl[Mz*Dz];     // (B,H,hd,L)
__device__ __align__(16) __nv_bfloat16 g_ah[(size_t)ZN*Lz*Lz], g_al[(size_t)ZN*Lz*Lz]; // attn hi/lo
__device__ __align__(16) __nv_bfloat16 g_ch[Mz*Dz], g_cl[Mz*Dz];       // ctx (B,L,D)

// ---------------- PTX helpers ----------------------------------------------------
__device__ __forceinline__ uint32_t smem_u32(const void* p) {
    uint32_t a;
    asm("{ .reg .u64 t; cvta.to.shared.u64 t, %1; cvt.u32.u64 %0, t; }" : "=r"(a) : "l"(p));
    return a;
}
__device__ __forceinline__ void cpasync16(uint32_t s, const void* g) {
    asm volatile("cp.async.cg.shared.global [%0], [%1], 16;" :: "r"(s), "l"(g));
}
#define CP_COMMIT()  asm volatile("cp.async.commit_group;" ::: "memory")
#define CP_WAIT1()   asm volatile("cp.async.wait_group 1;" ::: "memory")
#define CP_WAIT0()   asm volatile("cp.async.wait_group 0;" ::: "memory")

__device__ __forceinline__ void hmma(float* d, const uint32_t* a, const uint32_t* b) {
    asm volatile(
        "mma.sync.aligned.m16n8k16.row.col.f32.bf16.bf16.f32 "
        "{%0,%1,%2,%3}, {%4,%5,%6,%7}, {%8,%9}, {%0,%1,%2,%3};"
        : "+f"(d[0]), "+f"(d[1]), "+f"(d[2]), "+f"(d[3])
        : "r"(a[0]), "r"(a[1]), "r"(a[2]), "r"(a[3]), "r"(b[0]), "r"(b[1]));
}

__device__ __forceinline__ __nv_bfloat162 split_hi2(float x, float y,
                                                    __nv_bfloat162& lo2) {
    __nv_bfloat16 hx = __float2bfloat16(x);
    __nv_bfloat16 hy = __float2bfloat16(y);
    lo2 = __nv_bfloat162(__float2bfloat16(x - __bfloat162float(hx)),
                         __float2bfloat16(y - __bfloat162float(hy)));
    return __nv_bfloat162(hx, hy);
}

// ---------------- big-K HMMA GEMM (projections / output proj) ---------------------
// C = scale * A @ B^T + bias. A: M x K (K-major hi/lo), B: N x K (K-major hi/lo).
// LAYOUT 0: fp32 row-major. LAYOUT 1: fp32 head layout. LAYOUT 2: bf16 hi/lo head layout.
#define KC 32
#define ROWB 80
#define MAT_BYTES (128 * ROWB)
#define STAGE_BYTES (4 * MAT_BYTES)
#define HSMEM (2 * STAGE_BYTES)      // 81920

template<int LAYOUT>
__global__ __launch_bounds__(256) void hmma_gemm(
    const __nv_bfloat16* __restrict__ Ah, const __nv_bfloat16* __restrict__ Al,
    const __nv_bfloat16* __restrict__ Bh, const __nv_bfloat16* __restrict__ Bl,
    const float* __restrict__ bias, float* __restrict__ C,
    __nv_bfloat16* __restrict__ Ch, __nv_bfloat16* __restrict__ Cl,
    int K, int N, float scale)
{
    extern __shared__ char sm[];
    const uint32_t sbase = smem_u32(sm);

    const int tid  = threadIdx.x;
    const int warp = tid >> 5;
    const int lane = tid & 31;
    const int g = lane >> 2;
    const int t = lane & 3;
    const int wm = (warp >> 2) * 64;
    const int wn = (warp & 3) * 32;

    const int bm = blockIdx.y * 128;
    const int bn = blockIdx.x * 128;

    const __nv_bfloat16* tAh = Ah + (size_t)bm * K;
    const __nv_bfloat16* tAl = Al + (size_t)bm * K;
    const __nv_bfloat16* tBh = Bh + (size_t)bn * K;
    const __nv_bfloat16* tBl = Bl + (size_t)bn * K;

    const int r0 = tid >> 2;
    const int r1 = r0 + 64;
    const int sg = tid & 3;

    auto prefetch = [&](int c, int stage) {
        const uint32_t sb = sbase + stage * STAGE_BYTES;
        const size_t go0 = (size_t)r0 * K + c * KC + sg * 8;
        const size_t go1 = (size_t)r1 * K + c * KC + sg * 8;
        const uint32_t so0 = r0 * ROWB + sg * 16;
        const uint32_t so1 = r1 * ROWB + sg * 16;
        cpasync16(sb + 0 * MAT_BYTES + so0, tAh + go0);
        cpasync16(sb + 0 * MAT_BYTES + so1, tAh + go1);
        cpasync16(sb + 1 * MAT_BYTES + so0, tAl + go0);
        cpasync16(sb + 1 * MAT_BYTES + so1, tAl + go1);
        cpasync16(sb + 2 * MAT_BYTES + so0, tBh + go0);
        cpasync16(sb + 2 * MAT_BYTES + so1, tBh + go1);
        cpasync16(sb + 3 * MAT_BYTES + so0, tBl + go0);
        cpasync16(sb + 3 * MAT_BYTES + so1, tBl + go1);
    };

    float acc[4][4][4];
    #pragma unroll
    for (int i = 0; i < 4; i++)
        #pragma unroll
        for (int j = 0; j < 4; j++)
            #pragma unroll
            for (int k = 0; k < 4; k++) acc[i][j][k] = 0.0f;

    const int nch = K / KC;
    prefetch(0, 0); CP_COMMIT();
    prefetch(1, 1); CP_COMMIT();

    for (int c = 0; c < nch; c++) {
        if (c + 1 < nch) { CP_WAIT1(); } else { CP_WAIT0(); }
        __syncthreads();

        const uint32_t stofs = (c & 1) * STAGE_BYTES;
        const char* sAh = sm + stofs;
        const char* sAl = sAh + MAT_BYTES;
        const char* sBh = sAl + MAT_BYTES;
        const char* sBl = sBh + MAT_BYTES;

        #pragma unroll
        for (int kk = 0; kk < KC; kk += 16) {
            const uint32_t cofs = (kk + 2 * t) * 2;

            uint32_t bH[4][2], bL[4][2];
            #pragma unroll
            for (int nt = 0; nt < 4; nt++) {
                const uint32_t ro = (wn + nt * 8 + g) * ROWB + cofs;
                bH[nt][0] = *(const uint32_t*)(sBh + ro);
                bH[nt][1] = *(const uint32_t*)(sBh + ro + 16);
                bL[nt][0] = *(const uint32_t*)(sBl + ro);
                bL[nt][1] = *(const uint32_t*)(sBl + ro + 16);
            }

            #pragma unroll
            for (int mt = 0; mt < 4; mt++) {
                const uint32_t ro = (wm + mt * 16 + g) * ROWB + cofs;
                uint32_t aH[4], aL[4];
                aH[0] = *(const uint32_t*)(sAh + ro);
                aH[1] = *(const uint32_t*)(sAh + ro + 8 * ROWB);
                aH[2] = *(const uint32_t*)(sAh + ro + 16);
                aH[3] = *(const uint32_t*)(sAh + ro + 8 * ROWB + 16);
                aL[0] = *(const uint32_t*)(sAl + ro);
                aL[1] = *(const uint32_t*)(sAl + ro + 8 * ROWB);
                aL[2] = *(const uint32_t*)(sAl + ro + 16);
                aL[3] = *(const uint32_t*)(sAl + ro + 8 * ROWB + 16);

                #pragma unroll
                for (int nt = 0; nt < 4; nt++) {
                    hmma(acc[mt][nt], aH, bH[nt]);
                    hmma(acc[mt][nt], aH, bL[nt]);
                    hmma(acc[mt][nt], aL, bH[nt]);
                }
            }
        }

        __syncthreads();
        if (c + 2 < nch) { prefetch(c + 2, (c & 1)); CP_COMMIT(); }
        else { CP_COMMIT(); }
    }

    #pragma unroll
    for (int mt = 0; mt < 4; mt++) {
        const int m0 = bm + wm + mt * 16 + g;
        #pragma unroll
        for (int nt = 0; nt < 4; nt++) {
            const int n0 = bn + wn + nt * 8 + 2 * t;
            const float b0 = bias[n0], b1 = bias[n0 + 1];
            float v0 = acc[mt][nt][0] * scale + b0;
            float v1 = acc[mt][nt][1] * scale + b1;
            float v2 = acc[mt][nt][2] * scale + b0;
            float v3 = acc[mt][nt][3] * scale + b1;
            if (LAYOUT == 0) {
                *(float2*)&C[(size_t)m0 * N + n0]       = make_float2(v0, v1);
                *(float2*)&C[(size_t)(m0 + 8) * N + n0] = make_float2(v2, v3);
            } else if (LAYOUT == 1) {
                const int h = n0 >> 6, dd = n0 & 63;
                const int b = m0 >> 10, l = m0 & 1023;
                float* base = C + (((size_t)(b * Hz + h) * Lz) << 6) + dd;
                *(float2*)(base + ((size_t)l << 6))       = make_float2(v0, v1);
                *(float2*)(base + ((size_t)(l + 8) << 6)) = make_float2(v2, v3);
            } else {
                const int h = n0 >> 6, dd = n0 & 63;
                const int b = m0 >> 10, l = m0 & 1023;
                const size_t i0 = (((size_t)(b * Hz + h) * Lz + l)     << 6) + dd;
                const size_t i1 = (((size_t)(b * Hz + h) * Lz + l + 8) << 6) + dd;
                __nv_bfloat162 lo;
                __nv_bfloat162 hi = split_hi2(v0, v1, lo);
                *(__nv_bfloat162*)&Ch[i0] = hi;
                *(__nv_bfloat162*)&Cl[i0] = lo;
                hi = split_hi2(v2, v3, lo);
                *(__nv_bfloat162*)&Ch[i1] = hi;
                *(__nv_bfloat162*)&Cl[i1] = lo;
            }
        }
    }
}

// ---------------- scores HMMA: per (b,h), 1024x1024, K=64 -------------------------
#define SROW 144
#define SMAT (128 * SROW)      // 18432
#define SSMEM (4 * SMAT)       // 73728

__global__ __launch_bounds__(256) void scores_hmma(
    const __nv_bfloat16* __restrict__ qh, const __nv_bfloat16* __restrict__ ql,
    const __nv_bfloat16* __restrict__ kh, const __nv_bfloat16* __restrict__ kl,
    const float* __restrict__ bias, float* __restrict__ attn)
{
    extern __shared__ char sm[];
    const uint32_t sbase = smem_u32(sm);

    const int tid  = threadIdx.x;
    const int warp = tid >> 5;
    const int lane = tid & 31;
    const int g = lane >> 2;
    const int t = lane & 3;
    const int wm = (warp >> 2) * 64;
    const int wn = (warp & 3) * 32;

    const int z  = blockIdx.z;
    const int bm = blockIdx.y * 128;
    const int bn = blockIdx.x * 128;

    const size_t zofs = (size_t)z * Lz * HDz;
    const __nv_bfloat16* pqh = qh + zofs + (size_t)bm * HDz;
    const __nv_bfloat16* pql = ql + zofs + (size_t)bm * HDz;
    const __nv_bfloat16* pkh = kh + zofs + (size_t)bn * HDz;
    const __nv_bfloat16* pkl = kl + zofs + (size_t)bn * HDz;

    // load all 4 matrices: 128 rows x 128B, 1024 uint4 each, 4 per thread
    #pragma unroll
    for (int i = 0; i < 4; i++) {
        const int idx = tid + i * 256;
        const int row = idx >> 3, seg = idx & 7;
        const uint32_t off = row * SROW + seg * 16;
        const size_t go = (size_t)row * HDz + seg * 8;
        cpasync16(sbase + 0 * SMAT + off, pqh + go);
        cpasync16(sbase + 1 * SMAT + off, pql + go);
        cpasync16(sbase + 2 * SMAT + off, pkh + go);
        cpasync16(sbase + 3 * SMAT + off, pkl + go);
    }
    CP_COMMIT();
    CP_WAIT0();
    __syncthreads();

    float acc[4][4][4];
    #pragma unroll
    for (int i = 0; i < 4; i++)
        #pragma unroll
        for (int j = 0; j < 4; j++)
            #pragma unroll
            for (int k = 0; k < 4; k++) acc[i][j][k] = 0.0f;

    const char* sQh = sm;
    const char* sQl = sm + 1 * SMAT;
    const char* sKh = sm + 2 * SMAT;
    const char* sKl = sm + 3 * SMAT;

    #pragma unroll
    for (int kk = 0; kk < 64; kk += 16) {
        const uint32_t cofs = (kk + 2 * t) * 2;

        uint32_t bH[4][2], bL[4][2];
        #pragma unroll
        for (int nt = 0; nt < 4; nt++) {
            const uint32_t ro = (wn + nt * 8 + g) * SROW + cofs;
            bH[nt][0] = *(const uint32_t*)(sKh + ro);
            bH[nt][1] = *(const uint32_t*)(sKh + ro + 16);
            bL[nt][0] = *(const uint32_t*)(sKl + ro);
            bL[nt][1] = *(const uint32_t*)(sKl + ro + 16);
        }

        #pragma unroll
        for (int mt = 0; mt < 4; mt++) {
            const uint32_t ro = (wm + mt * 16 + g) * SROW + cofs;
            uint32_t aH[4], aL[4];
            aH[0] = *(const uint32_t*)(sQh + ro);
            aH[1] = *(const uint32_t*)(sQh + ro + 8 * SROW);
            aH[2] = *(const uint32_t*)(sQh + ro + 16);
            aH[3] = *(const uint32_t*)(sQh + ro + 8 * SROW + 16);
            aL[0] = *(const uint32_t*)(sQl + ro);
            aL[1] = *(const uint32_t*)(sQl + ro + 8 * SROW);
            aL[2] = *(const uint32_t*)(sQl + ro + 16);
            aL[3] = *(const uint32_t*)(sQl + ro + 8 * SROW + 16);

            #pragma unroll
            for (int nt = 0; nt < 4; nt++) {
                hmma(acc[mt][nt], aH, bH[nt]);
                hmma(acc[mt][nt], aH, bL[nt]);
                hmma(acc[mt][nt], aL, bH[nt]);
            }
        }
    }

    float* attnZ = attn + (size_t)z * Lz * Lz;
    #pragma unroll
    for (int mt = 0; mt < 4; mt++) {
        const int m0 = bm + wm + mt * 16 + g;
        #pragma unroll
        for (int nt = 0; nt < 4; nt++) {
            const int n0 = bn + wn + nt * 8 + 2 * t;
            const float b0 = bias[n0], b1 = bias[n0 + 1];
            *(float2*)&attnZ[(size_t)m0 * Lz + n0] =
                make_float2(acc[mt][nt][0] * 0.125f + b0, acc[mt][nt][1] * 0.125f + b1);
            *(float2*)&attnZ[(size_t)(m0 + 8) * Lz + n0] =
                make_float2(acc[mt][nt][2] * 0.125f + b0, acc[mt][nt][3] * 0.125f + b1);
        }
    }
}

// ---------------- AV HMMA: per (b,h), (1024x1024)@(1024x64) -----------------------
// A = attn hi/lo (K-major over m), B = vT hi/lo (d, m) K-major over m.
// CTA tile 128(m) x 64(d), K-chunk 64, double buffered. Writes ctx bf16 hi/lo (B,L,D).
#define AROW 144
#define AV_AMAT (128 * AROW)                 // 18432
#define AV_BMAT (64 * AROW)                  // 9216
#define AV_STAGE (2 * AV_AMAT + 2 * AV_BMAT) // 55296
#define AVSMEM (2 * AV_STAGE)                // 110592

__global__ __launch_bounds__(256) void av_hmma(
    const __nv_bfloat16* __restrict__ ah, const __nv_bfloat16* __restrict__ al,
    const __nv_bfloat16* __restrict__ vth, const __nv_bfloat16* __restrict__ vtl,
    __nv_bfloat16* __restrict__ Ch, __nv_bfloat16* __restrict__ Cl)
{
    extern __shared__ char sm[];
    const uint32_t sbase = smem_u32(sm);

    const int tid  = threadIdx.x;
    const int warp = tid >> 5;
    const int lane = tid & 31;
    const int g = lane >> 2;
    const int t = lane & 3;
    const int wm = (warp & 3) * 32;     // 4 m-warps
    const int wn = (warp >> 2) * 32;    // 2 n-warps

    const int z  = blockIdx.z;
    const int bm = blockIdx.y * 128;

    const __nv_bfloat16* pah = ah + (size_t)z * Lz * Lz + (size_t)bm * Lz;
    const __nv_bfloat16* pal = al + (size_t)z * Lz * Lz + (size_t)bm * Lz;
    const __nv_bfloat16* pvh = vth + (size_t)z * HDz * Lz;
    const __nv_bfloat16* pvl = vtl + (size_t)z * HDz * Lz;

    auto prefetch = [&](int c, int stage) {
        const uint32_t sb = sbase + stage * AV_STAGE;
        // A hi/lo: 1024 uint4 each -> 4 per thread
        #pragma unroll
        for (int i = 0; i < 4; i++) {
            const int idx = tid + i * 256;
            const int row = idx >> 3, seg = idx & 7;
            const uint32_t off = row * AROW + seg * 16;
            const size_t go = (size_t)row * Lz + c * 64 + seg * 8;
            cpasync16(sb + off, pah + go);
            cpasync16(sb + AV_AMAT + off, pal + go);
        }
        // B hi/lo: 512 uint4 each -> 2 per thread
        #pragma unroll
        for (int i = 0; i < 2; i++) {
            const int idx = tid + i * 256;
            const int row = idx >> 3, seg = idx & 7;
            const uint32_t off = row * AROW + seg * 16;
            const size_t go = (size_t)row * Lz + c * 64 + seg * 8;
            cpasync16(sb + 2 * AV_AMAT + off, pvh + go);
            cpasync16(sb + 2 * AV_AMAT + AV_BMAT + off, pvl + go);
        }
    };

    float acc[2][4][4];
    #pragma unroll
    for (int i = 0; i < 2; i++)
        #pragma unroll
        for (int j = 0; j < 4; j++)
            #pragma unroll
            for (int k = 0; k < 4; k++) acc[i][j][k] = 0.0f;

    const int nch = Lz / 64;   // 16
    prefetch(0, 0); CP_COMMIT();
    prefetch(1, 1); CP_COMMIT();

    for (int c = 0; c < nch; c++) {
        if (c + 1 < nch) { CP_WAIT1(); } else { CP_WAIT0(); }
        __syncthreads();

        const char* sb  = sm + (c & 1) * AV_STAGE;
        const char* sAh = sb;
        const char* sAl = sb + AV_AMAT;
        const char* sBh = sb + 2 * AV_AMAT;
        const char* sBl = sBh + AV_BMAT;

        #pragma unroll
        for (int kk = 0; kk < 64; kk += 16) {
            const uint32_t cofs = (kk + 2 * t) * 2;

            uint32_t bH[4][2], bL[4][2];
            #pragma unroll
            for (int nt = 0; nt < 4; nt++) {
                const uint32_t ro = (wn + nt * 8 + g) * AROW + cofs;
                bH[nt][0] = *(const uint32_t*)(sBh + ro);
                bH[nt][1] = *(const uint32_t*)(sBh + ro + 16);
                bL[nt][0] = *(const uint32_t*)(sBl + ro);
                bL[nt][1] = *(const uint32_t*)(sBl + ro + 16);
            }

            #pragma unroll
            for (int mt = 0; mt < 2; mt++) {
                const uint32_t ro = (wm + mt * 16 + g) * AROW + cofs;
                uint32_t aH[4], aL[4];
                aH[0] = *(const uint32_t*)(sAh + ro);
                aH[1] = *(const uint32_t*)(sAh + ro + 8 * AROW);
                aH[2] = *(const uint32_t*)(sAh + ro + 16);
                aH[3] = *(const uint32_t*)(sAh + ro + 8 * AROW + 16);
                aL[0] = *(const uint32_t*)(sAl + ro);
                aL[1] = *(const uint32_t*)(sAl + ro + 8 * AROW);
                aL[2] = *(const uint32_t*)(sAl + ro + 16);
                aL[3] = *(const uint32_t*)(sAl + ro + 8 * AROW + 16);

                #pragma unroll
                for (int nt = 0; nt < 4; nt++) {
                    hmma(acc[mt][nt], aH, bH[nt]);
                    hmma(acc[mt][nt], aH, bL[nt]);
                    hmma(acc[mt][nt], aL, bH[nt]);
                }
            }
        }

        __syncthreads();
        if (c + 2 < nch) { prefetch(c + 2, (c & 1)); CP_COMMIT(); }
        else { CP_COMMIT(); }
    }

    const int b = z >> 4, h = z & 15;
    #pragma unroll
    for (int mt = 0; mt < 2; mt++) {
        const int m0 = bm + wm + mt * 16 + g;
        #pragma unroll
        for (int nt = 0; nt < 4; nt++) {
            const int n0 = wn + nt * 8 + 2 * t;
            const size_t i0 = ((size_t)(b * Lz + m0)     << 10) + h * HDz + n0;
            const size_t i1 = ((size_t)(b * Lz + m0 + 8) << 10) + h * HDz + n0;
            __nv_bfloat162 lo;
            __nv_bfloat162 hi = split_hi2(acc[mt][nt][0], acc[mt][nt][1], lo);
            *(__nv_bfloat162*)&Ch[i0] = hi;
            *(__nv_bfloat162*)&Cl[i0] = lo;
            hi = split_hi2(acc[mt][nt][2], acc[mt][nt][3], lo);
            *(__nv_bfloat162*)&Ch[i1] = hi;
            *(__nv_bfloat162*)&Cl[i1] = lo;
        }
    }
}

// ---------------- softmax fused with bf16 split -----------------------------------
__global__ __launch_bounds__(256) void softmax_split_kernel(
    float* __restrict__ attn, __nv_bfloat16* __restrict__ ah,
    __nv_bfloat16* __restrict__ al)
{
    const size_t row = blockIdx.x;
    float4* p = reinterpret_cast<float4*>(attn + row * Lz);
    const int tid = threadIdx.x;
    __shared__ float red[8];

    float4 v = p[tid];
    float m = fmaxf(fmaxf(v.x, v.y), fmaxf(v.z, v.w));
    #pragma unroll
    for (int o = 16; o > 0; o >>= 1) m = fmaxf(m, __shfl_xor_sync(0xFFFFFFFFu, m, o));
    if ((tid & 31) == 0) red[tid >> 5] = m;
    __syncthreads();
    m = red[0];
    #pragma unroll
    for (int i = 1; i < 8; i++) m = fmaxf(m, red[i]);
    __syncthreads();

    v.x = expf(v.x - m); v.y = expf(v.y - m);
    v.z = expf(v.z - m); v.w = expf(v.w - m);
    float s = v.x + v.y + v.z + v.w;
    #pragma unroll
    for (int o = 16; o > 0; o >>= 1) s += __shfl_xor_sync(0xFFFFFFFFu, s, o);
    if ((tid & 31) == 0) red[tid >> 5] = s;
    __syncthreads();
    s = red[0];
    #pragma unroll
    for (int i = 1; i < 8; i++) s += red[i];

    float inv = 1.0f / s;
    v.x *= inv; v.y *= inv; v.z *= inv; v.w *= inv;
    p[tid] = v;

    __nv_bfloat162* H = reinterpret_cast<__nv_bfloat162*>(ah + row * Lz);
    __nv_bfloat162* L = reinterpret_cast<__nv_bfloat162*>(al + row * Lz);
    __nv_bfloat162 lo;
    __nv_bfloat162 hi = split_hi2(v.x, v.y, lo);
    H[tid * 2]     = hi; L[tid * 2]     = lo;
    hi = split_hi2(v.z, v.w, lo);
    H[tid * 2 + 1] = hi; L[tid * 2 + 1] = lo;
}

// ---------------- V transpose + split: (B,H,L,hd) fp32 -> (B,H,hd,L) bf16 hi/lo ---
__global__ __launch_bounds__(256) void tsplit_v(
    const float* __restrict__ v, __nv_bfloat16* __restrict__ vth,
    __nv_bfloat16* __restrict__ vtl)
{
    __shared__ float tile[32][33];
    const int z  = blockIdx.z;
    const int l0 = blockIdx.x * 32;
    const int d0 = blockIdx.y * 32;
    const int tx = threadIdx.x & 31;
    const int ty = threadIdx.x >> 5;   // 0..7

    const float* src = v + (size_t)z * Lz * HDz;
    #pragma unroll
    for (int j = 0; j < 4; j++)
        tile[ty + j * 8][tx] = src[(size_t)(l0 + ty + j * 8) * HDz + d0 + tx];
    __syncthreads();

    __nv_bfloat16* dh = vth + (size_t)z * HDz * Lz;
    __nv_bfloat16* dl = vtl + (size_t)z * HDz * Lz;
    #pragma unroll
    for (int j = 0; j < 4; j++) {
        const float val = tile[tx][ty + j * 8];
        const __nv_bfloat16 h = __float2bfloat16(val);
        const size_t o = (size_t)(d0 + ty + j * 8) * Lz + l0 + tx;
        dh[o] = h;
        dl[o] = __float2bfloat16(val - __bfloat162float(h));
    }
}

// ---------------- misc small kernels ----------------------------------------------
__global__ __launch_bounds__(256) void split_kernel(
    const float* __restrict__ in, __nv_bfloat16* __restrict__ hi,
    __nv_bfloat16* __restrict__ lo, int n4)
{
    int i = blockIdx.x * blockDim.x + threadIdx.x;
    if (i < n4) {
        float4 v = ((const float4*)in)[i];
        __nv_bfloat162* H = (__nv_bfloat162*)hi;
        __nv_bfloat162* L = (__nv_bfloat162*)lo;
        __nv_bfloat162 l2;
        H[i*2+0] = split_hi2(v.x, v.y, l2); L[i*2+0] = l2;
        H[i*2+1] = split_hi2(v.z, v.w, l2); L[i*2+1] = l2;
    }
}

__global__ void bias_kernel(const float* __restrict__ field,
                            const float* __restrict__ strength,
                            float* __restrict__ bias)
{
    int m = blockIdx.x * blockDim.x + threadIdx.x;
    if (m < Lz) {
        const float pi = 3.14159265358979323846f;
        float acc = 0.0f;
        #pragma unroll
        for (int i = 0; i < ORDERz; i++) {
            float sig = 1.0f / (1.0f + expf(-field[i * Lz + m]));
            acc += strength[i] * sinf((float)m * (float)(i + 1) * pi / (float)Lz) * sig;
        }
        bias[m] = acc;
    }
}

__global__ void energy_kernel(const float* __restrict__ s, float* __restrict__ e)
{
    e[0] = (s[0] * s[0] + s[1] * s[1] + s[2] * s[2]) * (1.0f / 3.0f);
}

// ---------------- launch ------------------------------------------------------------
extern "C" void kernel_launch(void* const* d_in, const int* in_sizes, int n_in,
                              void* d_out, int out_size)
{
    const float* x  = (const float*)d_in[0];
    const float* Wq = (const float*)d_in[1];
    const float* bq = (const float*)d_in[2];
    const float* Wk = (const float*)d_in[3];
    const float* bk = (const float*)d_in[4];
    const float* Wv = (const float*)d_in[5];
    const float* bv = (const float*)d_in[6];
    const float* Wo = (const float*)d_in[7];
    const float* bo = (const float*)d_in[8];
    const float* tf = (const float*)d_in[9];
    const float* ts = (const float*)d_in[10];

    float* out    = (float*)d_out;
    float* attn   = out + (size_t)Bz * Lz * Dz;
    float* energy = attn + (size_t)ZN * Lz * Lz;

    float *gv, *gbias;
    cudaGetSymbolAddress((void**)&gv,    g_v);
    cudaGetSymbolAddress((void**)&gbias, g_bias);

    __nv_bfloat16 *xh, *xl, *wh, *wl, *qh, *ql, *kh, *kl, *vth, *vtl, *ah, *al, *ch, *cl;
    cudaGetSymbolAddress((void**)&xh,  g_xh);
    cudaGetSymbolAddress((void**)&xl,  g_xl);
    cudaGetSymbolAddress((void**)&wh,  g_wh);
    cudaGetSymbolAddress((void**)&wl,  g_wl);
    cudaGetSymbolAddress((void**)&qh,  g_qh);
    cudaGetSymbolAddress((void**)&ql,  g_ql);
    cudaGetSymbolAddress((void**)&kh,  g_kh);
    cudaGetSymbolAddress((void**)&kl,  g_kl);
    cudaGetSymbolAddress((void**)&vth, g_vth);
    cudaGetSymbolAddress((void**)&vtl, g_vtl);
    cudaGetSymbolAddress((void**)&ah,  g_ah);
    cudaGetSymbolAddress((void**)&al,  g_al);
    cudaGetSymbolAddress((void**)&ch,  g_ch);
    cudaGetSymbolAddress((void**)&cl,  g_cl);

    cudaFuncSetAttribute(hmma_gemm<0>, cudaFuncAttributeMaxDynamicSharedMemorySize, HSMEM);
    cudaFuncSetAttribute(hmma_gemm<1>, cudaFuncAttributeMaxDynamicSharedMemorySize, HSMEM);
    cudaFuncSetAttribute(hmma_gemm<2>, cudaFuncAttributeMaxDynamicSharedMemorySize, HSMEM);
    cudaFuncSetAttribute(scores_hmma,  cudaFuncAttributeMaxDynamicSharedMemorySize, SSMEM);
    cudaFuncSetAttribute(av_hmma,      cudaFuncAttributeMaxDynamicSharedMemorySize, AVSMEM);

    bias_kernel<<<4, 256>>>(tf, ts, gbias);
    energy_kernel<<<1, 1>>>(ts, energy);

    const size_t WN = (size_t)Dz * Dz;
    split_kernel<<<(Mz*Dz/4 + 255)/256, 256>>>(x,  xh, xl, Mz*Dz/4);
    split_kernel<<<(WN/4 + 255)/256, 256>>>(Wq, wh + 0*WN, wl + 0*WN, WN/4);
    split_kernel<<<(WN/4 + 255)/256, 256>>>(Wk, wh + 1*WN, wl + 1*WN, WN/4);
    split_kernel<<<(WN/4 + 255)/256, 256>>>(Wv, wh + 2*WN, wl + 2*WN, WN/4);
    split_kernel<<<(WN/4 + 255)/256, 256>>>(Wo, wh + 3*WN, wl + 3*WN, WN/4);

    // Q/K projections -> bf16 hi/lo head layout; V -> fp32 head layout
    dim3 gproj(Dz / 128, Mz / 128);   // (8, 32)
    hmma_gemm<2><<<gproj, 256, HSMEM>>>(xh, xl, wh + 0*WN, wl + 0*WN, bq, nullptr, qh, ql, Dz, Dz, 1.0f);
    hmma_gemm<2><<<gproj, 256, HSMEM>>>(xh, xl, wh + 1*WN, wl + 1*WN, bk, nullptr, kh, kl, Dz, Dz, 1.0f);
    hmma_gemm<1><<<gproj, 256, HSMEM>>>(xh, xl, wh + 2*WN, wl + 2*WN, bv, gv, nullptr, nullptr, Dz, Dz, 1.0f);

    // V transpose + split -> (B,H,hd,L)
    tsplit_v<<<dim3(Lz/32, HDz/32, ZN), 256>>>(gv, vth, vtl);

    // scores on tensor cores
    scores_hmma<<<dim3(8, 8, ZN), 256, SSMEM>>>(qh, ql, kh, kl, gbias, attn);

    // softmax + bf16 split of attn
    softmax_split_kernel<<<ZN * Lz, 256>>>(attn, ah, al);

    // AV on tensor cores -> ctx bf16 hi/lo
    av_hmma<<<dim3(1, 8, ZN), 256, AVSMEM>>>(ah, al, vth, vtl, ch, cl);

    // out = ctx @ Wo^T + bo
    hmma_gemm<0><<<gproj, 256, HSMEM>>>(ch, cl, wh + 3*WN, wl + 3*WN, bo, out, nullptr, nullptr, Dz, Dz, 1.0f);
}

// round 6
// speedup vs baseline: 2.9924x; 1.0896x over previous
#include <cuda_runtime.h>
#include <cuda_bf16.h>
#include <math.h>
#include <stdint.h>

#define Bz   4
#define Lz   1024
#define Dz   1024
#define Hz   16
#define HDz  64
#define Mz   (Bz*Lz)          // 4096
#define ORDERz 3
#define ZN   (Bz*Hz)          // 64

// ---------------- scratch (__device__ globals) ----------------------------------
__device__ __align__(16) float g_v[Mz*Dz];     // (B,H,L,hd) fp32
__device__ __align__(16) float g_bias[Lz];

__device__ __align__(16) __nv_bfloat16 g_xh[Mz*Dz], g_xl[Mz*Dz];
__device__ __align__(16) __nv_bfloat16 g_wh[4][Dz*Dz], g_wl[4][Dz*Dz]; // q,k,v,o
__device__ __align__(16) __nv_bfloat16 g_qh[Mz*Dz], g_ql[Mz*Dz];       // (B,H,L,hd)
__device__ __align__(16) __nv_bfloat16 g_kh[Mz*Dz], g_kl[Mz*Dz];       // (B,H,L,hd)
__device__ __align__(16) __nv_bfloat16 g_vth[Mz*Dz], g_vtl[Mz*Dz];     // (B,H,hd,L)
__device__ __align__(16) __nv_bfloat16 g_ah[(size_t)ZN*Lz*Lz], g_al[(size_t)ZN*Lz*Lz];
__device__ __align__(16) __nv_bfloat16 g_ch[Mz*Dz], g_cl[Mz*Dz];       // ctx (B,L,D)

// ---------------- PTX helpers ----------------------------------------------------
__device__ __forceinline__ uint32_t smem_u32(const void* p) {
    uint32_t a;
    asm("{ .reg .u64 t; cvta.to.shared.u64 t, %1; cvt.u32.u64 %0, t; }" : "=r"(a) : "l"(p));
    return a;
}
__device__ __forceinline__ void cpasync16(uint32_t s, const void* g) {
    asm volatile("cp.async.cg.shared.global [%0], [%1], 16;" :: "r"(s), "l"(g));
}
#define CP_COMMIT()  asm volatile("cp.async.commit_group;" ::: "memory")
#define CP_WAIT1()   asm volatile("cp.async.wait_group 1;" ::: "memory")
#define CP_WAIT0()   asm volatile("cp.async.wait_group 0;" ::: "memory")

__device__ __forceinline__ void hmma(float* d, const uint32_t* a, const uint32_t* b) {
    asm volatile(
        "mma.sync.aligned.m16n8k16.row.col.f32.bf16.bf16.f32 "
        "{%0,%1,%2,%3}, {%4,%5,%6,%7}, {%8,%9}, {%0,%1,%2,%3};"
        : "+f"(d[0]), "+f"(d[1]), "+f"(d[2]), "+f"(d[3])
        : "r"(a[0]), "r"(a[1]), "r"(a[2]), "r"(a[3]), "r"(b[0]), "r"(b[1]));
}
__device__ __forceinline__ void ldsm_x4(uint32_t* r, uint32_t saddr) {
    asm volatile("ldmatrix.sync.aligned.m8n8.x4.shared.b16 {%0,%1,%2,%3}, [%4];"
        : "=r"(r[0]), "=r"(r[1]), "=r"(r[2]), "=r"(r[3]) : "r"(saddr));
}
__device__ __forceinline__ void ldsm_x2(uint32_t* r, uint32_t saddr) {
    asm volatile("ldmatrix.sync.aligned.m8n8.x2.shared.b16 {%0,%1}, [%2];"
        : "=r"(r[0]), "=r"(r[1]) : "r"(saddr));
}

__device__ __forceinline__ __nv_bfloat162 split_hi2(float x, float y,
                                                    __nv_bfloat162& lo2) {
    __nv_bfloat16 hx = __float2bfloat16(x);
    __nv_bfloat16 hy = __float2bfloat16(y);
    lo2 = __nv_bfloat162(__float2bfloat16(x - __bfloat162float(hx)),
                         __float2bfloat16(y - __bfloat162float(hy)));
    return __nv_bfloat162(hx, hy);
}

// ldmatrix per-lane row-offset helpers (row stride RS bytes):
// A (x4): matrices [m0-7,k0-15-lo16B][m8-15,lo][m0-7,hi16B][m8-15,hi]
__device__ __forceinline__ uint32_t a_ldsm_off(int lane, int RS) {
    return (uint32_t)((lane & 7) * RS + ((lane >> 3) & 1) * 8 * RS + ((lane >> 4) & 1) * 16);
}
// B (x2): matrices [n0-7,k lo16B][n0-7,k hi16B]; lanes 16-31 mirror 0-15
__device__ __forceinline__ uint32_t b_ldsm_off(int lane, int RS) {
    const int l = lane & 15;
    return (uint32_t)((l & 7) * RS + ((l >> 3) & 1) * 16);
}

// ---------------- big-K HMMA GEMM (projections / output proj) ---------------------
#define KC 32
#define ROWB 80
#define MAT_BYTES (128 * ROWB)
#define STAGE_BYTES (4 * MAT_BYTES)
#define HSMEM (2 * STAGE_BYTES)      // 81920

template<int LAYOUT>
__global__ __launch_bounds__(256, 2) void hmma_gemm(
    const __nv_bfloat16* __restrict__ Ah, const __nv_bfloat16* __restrict__ Al,
    const __nv_bfloat16* __restrict__ Bh, const __nv_bfloat16* __restrict__ Bl,
    const float* __restrict__ bias, float* __restrict__ C,
    __nv_bfloat16* __restrict__ Ch, __nv_bfloat16* __restrict__ Cl,
    int K, int N, float scale)
{
    extern __shared__ char sm[];
    const uint32_t sbase = smem_u32(sm);

    const int tid  = threadIdx.x;
    const int warp = tid >> 5;
    const int lane = tid & 31;
    const int g = lane >> 2;
    const int t = lane & 3;
    const int wm = (warp >> 2) * 64;
    const int wn = (warp & 3) * 32;

    const int bm = blockIdx.y * 128;
    const int bn = blockIdx.x * 128;

    const __nv_bfloat16* tAh = Ah + (size_t)bm * K;
    const __nv_bfloat16* tAl = Al + (size_t)bm * K;
    const __nv_bfloat16* tBh = Bh + (size_t)bn * K;
    const __nv_bfloat16* tBl = Bl + (size_t)bn * K;

    const int r0 = tid >> 2;
    const int r1 = r0 + 64;
    const int sg = tid & 3;

    const uint32_t aOff = a_ldsm_off(lane, ROWB);
    const uint32_t bOff = b_ldsm_off(lane, ROWB);

    auto prefetch = [&](int c, int stage) {
        const uint32_t sb = sbase + stage * STAGE_BYTES;
        const size_t go0 = (size_t)r0 * K + c * KC + sg * 8;
        const size_t go1 = (size_t)r1 * K + c * KC + sg * 8;
        const uint32_t so0 = r0 * ROWB + sg * 16;
        const uint32_t so1 = r1 * ROWB + sg * 16;
        cpasync16(sb + 0 * MAT_BYTES + so0, tAh + go0);
        cpasync16(sb + 0 * MAT_BYTES + so1, tAh + go1);
        cpasync16(sb + 1 * MAT_BYTES + so0, tAl + go0);
        cpasync16(sb + 1 * MAT_BYTES + so1, tAl + go1);
        cpasync16(sb + 2 * MAT_BYTES + so0, tBh + go0);
        cpasync16(sb + 2 * MAT_BYTES + so1, tBh + go1);
        cpasync16(sb + 3 * MAT_BYTES + so0, tBl + go0);
        cpasync16(sb + 3 * MAT_BYTES + so1, tBl + go1);
    };

    float acc[4][4][4];
    #pragma unroll
    for (int i = 0; i < 4; i++)
        #pragma unroll
        for (int j = 0; j < 4; j++)
            #pragma unroll
            for (int k = 0; k < 4; k++) acc[i][j][k] = 0.0f;

    const int nch = K / KC;
    prefetch(0, 0); CP_COMMIT();
    prefetch(1, 1); CP_COMMIT();

    for (int c = 0; c < nch; c++) {
        if (c + 1 < nch) { CP_WAIT1(); } else { CP_WAIT0(); }
        __syncthreads();

        const uint32_t sb  = sbase + (c & 1) * STAGE_BYTES;
        const uint32_t sAh = sb;
        const uint32_t sAl = sb + 1 * MAT_BYTES;
        const uint32_t sBh = sb + 2 * MAT_BYTES;
        const uint32_t sBl = sb + 3 * MAT_BYTES;

        #pragma unroll
        for (int kk = 0; kk < KC; kk += 16) {
            const uint32_t kb = kk * 2;

            uint32_t bH[4][2], bL[4][2];
            #pragma unroll
            for (int nt = 0; nt < 4; nt++) {
                const uint32_t ro = (wn + nt * 8) * ROWB + kb + bOff;
                ldsm_x2(bH[nt], sBh + ro);
                ldsm_x2(bL[nt], sBl + ro);
            }

            #pragma unroll
            for (int mt = 0; mt < 4; mt++) {
                const uint32_t ro = (wm + mt * 16) * ROWB + kb + aOff;
                uint32_t aH[4], aL[4];
                ldsm_x4(aH, sAh + ro);
                ldsm_x4(aL, sAl + ro);

                #pragma unroll
                for (int nt = 0; nt < 4; nt++) {
                    hmma(acc[mt][nt], aH, bH[nt]);
                    hmma(acc[mt][nt], aH, bL[nt]);
                    hmma(acc[mt][nt], aL, bH[nt]);
                }
            }
        }

        __syncthreads();
        if (c + 2 < nch) { prefetch(c + 2, (c & 1)); CP_COMMIT(); }
        else { CP_COMMIT(); }
    }

    #pragma unroll
    for (int mt = 0; mt < 4; mt++) {
        const int m0 = bm + wm + mt * 16 + g;
        #pragma unroll
        for (int nt = 0; nt < 4; nt++) {
            const int n0 = bn + wn + nt * 8 + 2 * t;
            const float b0 = bias[n0], b1 = bias[n0 + 1];
            float v0 = acc[mt][nt][0] * scale + b0;
            float v1 = acc[mt][nt][1] * scale + b1;
            float v2 = acc[mt][nt][2] * scale + b0;
            float v3 = acc[mt][nt][3] * scale + b1;
            if (LAYOUT == 0) {
                *(float2*)&C[(size_t)m0 * N + n0]       = make_float2(v0, v1);
                *(float2*)&C[(size_t)(m0 + 8) * N + n0] = make_float2(v2, v3);
            } else if (LAYOUT == 1) {
                const int h = n0 >> 6, dd = n0 & 63;
                const int b = m0 >> 10, l = m0 & 1023;
                float* base = C + (((size_t)(b * Hz + h) * Lz) << 6) + dd;
                *(float2*)(base + ((size_t)l << 6))       = make_float2(v0, v1);
                *(float2*)(base + ((size_t)(l + 8) << 6)) = make_float2(v2, v3);
            } else {
                const int h = n0 >> 6, dd = n0 & 63;
                const int b = m0 >> 10, l = m0 & 1023;
                const size_t i0 = (((size_t)(b * Hz + h) * Lz + l)     << 6) + dd;
                const size_t i1 = (((size_t)(b * Hz + h) * Lz + l + 8) << 6) + dd;
                __nv_bfloat162 lo;
                __nv_bfloat162 hi = split_hi2(v0, v1, lo);
                *(__nv_bfloat162*)&Ch[i0] = hi;
                *(__nv_bfloat162*)&Cl[i0] = lo;
                hi = split_hi2(v2, v3, lo);
                *(__nv_bfloat162*)&Ch[i1] = hi;
                *(__nv_bfloat162*)&Cl[i1] = lo;
            }
        }
    }
}

// ---------------- scores HMMA: per (b,h), 1024x1024, K=64 -------------------------
#define SROW 144
#define SMAT (128 * SROW)      // 18432
#define SSMEM (4 * SMAT)       // 73728

__global__ __launch_bounds__(256, 2) void scores_hmma(
    const __nv_bfloat16* __restrict__ qh, const __nv_bfloat16* __restrict__ ql,
    const __nv_bfloat16* __restrict__ kh, const __nv_bfloat16* __restrict__ kl,
    const float* __restrict__ bias, float* __restrict__ attn)
{
    extern __shared__ char sm[];
    const uint32_t sbase = smem_u32(sm);

    const int tid  = threadIdx.x;
    const int warp = tid >> 5;
    const int lane = tid & 31;
    const int g = lane >> 2;
    const int t = lane & 3;
    const int wm = (warp >> 2) * 64;
    const int wn = (warp & 3) * 32;

    const int z  = blockIdx.z;
    const int bm = blockIdx.y * 128;
    const int bn = blockIdx.x * 128;

    const size_t zofs = (size_t)z * Lz * HDz;
    const __nv_bfloat16* pqh = qh + zofs + (size_t)bm * HDz;
    const __nv_bfloat16* pql = ql + zofs + (size_t)bm * HDz;
    const __nv_bfloat16* pkh = kh + zofs + (size_t)bn * HDz;
    const __nv_bfloat16* pkl = kl + zofs + (size_t)bn * HDz;

    #pragma unroll
    for (int i = 0; i < 4; i++) {
        const int idx = tid + i * 256;
        const int row = idx >> 3, seg = idx & 7;
        const uint32_t off = row * SROW + seg * 16;
        const size_t go = (size_t)row * HDz + seg * 8;
        cpasync16(sbase + 0 * SMAT + off, pqh + go);
        cpasync16(sbase + 1 * SMAT + off, pql + go);
        cpasync16(sbase + 2 * SMAT + off, pkh + go);
        cpasync16(sbase + 3 * SMAT + off, pkl + go);
    }
    CP_COMMIT();
    CP_WAIT0();
    __syncthreads();

    float acc[4][4][4];
    #pragma unroll
    for (int i = 0; i < 4; i++)
        #pragma unroll
        for (int j = 0; j < 4; j++)
            #pragma unroll
            for (int k = 0; k < 4; k++) acc[i][j][k] = 0.0f;

    const uint32_t sQh = sbase;
    const uint32_t sQl = sbase + 1 * SMAT;
    const uint32_t sKh = sbase + 2 * SMAT;
    const uint32_t sKl = sbase + 3 * SMAT;

    const uint32_t aOff = a_ldsm_off(lane, SROW);
    const uint32_t bOff = b_ldsm_off(lane, SROW);

    #pragma unroll
    for (int kk = 0; kk < 64; kk += 16) {
        const uint32_t kb = kk * 2;

        uint32_t bH[4][2], bL[4][2];
        #pragma unroll
        for (int nt = 0; nt < 4; nt++) {
            const uint32_t ro = (wn + nt * 8) * SROW + kb + bOff;
            ldsm_x2(bH[nt], sKh + ro);
            ldsm_x2(bL[nt], sKl + ro);
        }

        #pragma unroll
        for (int mt = 0; mt < 4; mt++) {
            const uint32_t ro = (wm + mt * 16) * SROW + kb + aOff;
            uint32_t aH[4], aL[4];
            ldsm_x4(aH, sQh + ro);
            ldsm_x4(aL, sQl + ro);

            #pragma unroll
            for (int nt = 0; nt < 4; nt++) {
                hmma(acc[mt][nt], aH, bH[nt]);
                hmma(acc[mt][nt], aH, bL[nt]);
                hmma(acc[mt][nt], aL, bH[nt]);
            }
        }
    }

    float* attnZ = attn + (size_t)z * Lz * Lz;
    #pragma unroll
    for (int mt = 0; mt < 4; mt++) {
        const int m0 = bm + wm + mt * 16 + g;
        #pragma unroll
        for (int nt = 0; nt < 4; nt++) {
            const int n0 = bn + wn + nt * 8 + 2 * t;
            const float b0 = bias[n0], b1 = bias[n0 + 1];
            *(float2*)&attnZ[(size_t)m0 * Lz + n0] =
                make_float2(acc[mt][nt][0] * 0.125f + b0, acc[mt][nt][1] * 0.125f + b1);
            *(float2*)&attnZ[(size_t)(m0 + 8) * Lz + n0] =
                make_float2(acc[mt][nt][2] * 0.125f + b0, acc[mt][nt][3] * 0.125f + b1);
        }
    }
}

// ---------------- AV HMMA: per (b,h), (1024x1024)@(1024x64) -----------------------
// CTA tile 256(m) x 64(d), K-chunk 32. Grid = 256 CTAs -> single wave at 2 CTA/SM.
#define AROW 80
#define AV_AMAT (256 * AROW)                 // 20480
#define AV_BMAT (64 * AROW)                  // 5120
#define AV_STAGE (2 * AV_AMAT + 2 * AV_BMAT) // 51200
#define AVSMEM (2 * AV_STAGE)                // 102400

__global__ __launch_bounds__(256, 2) void av_hmma(
    const __nv_bfloat16* __restrict__ ah, const __nv_bfloat16* __restrict__ al,
    const __nv_bfloat16* __restrict__ vth, const __nv_bfloat16* __restrict__ vtl,
    __nv_bfloat16* __restrict__ Ch, __nv_bfloat16* __restrict__ Cl)
{
    extern __shared__ char sm[];
    const uint32_t sbase = smem_u32(sm);

    const int tid  = threadIdx.x;
    const int warp = tid >> 5;
    const int lane = tid & 31;
    const int g = lane >> 2;
    const int t = lane & 3;
    const int wm = warp * 32;          // 8 m-warps, 32 rows each

    const int z  = blockIdx.z;
    const int bm = blockIdx.y * 256;

    const __nv_bfloat16* pah = ah + (size_t)z * Lz * Lz + (size_t)bm * Lz;
    const __nv_bfloat16* pal = al + (size_t)z * Lz * Lz + (size_t)bm * Lz;
    const __nv_bfloat16* pvh = vth + (size_t)z * HDz * Lz;
    const __nv_bfloat16* pvl = vtl + (size_t)z * HDz * Lz;

    const uint32_t aOff = a_ldsm_off(lane, AROW);
    const uint32_t bOff = b_ldsm_off(lane, AROW);

    auto prefetch = [&](int c, int stage) {
        const uint32_t sb = sbase + stage * AV_STAGE;
        // A hi/lo: 256 rows x 64B -> 1024 uint4 each -> 4 per thread
        #pragma unroll
        for (int i = 0; i < 4; i++) {
            const int idx = tid + i * 256;
            const int row = idx >> 2, seg = idx & 3;
            const uint32_t off = row * AROW + seg * 16;
            const size_t go = (size_t)row * Lz + c * 32 + seg * 8;
            cpasync16(sb + off, pah + go);
            cpasync16(sb + AV_AMAT + off, pal + go);
        }
        // B hi/lo: 64 rows x 64B -> 256 uint4 each -> 1 per thread
        {
            const int row = tid >> 2, seg = tid & 3;
            const uint32_t off = row * AROW + seg * 16;
            const size_t go = (size_t)row * Lz + c * 32 + seg * 8;
            cpasync16(sb + 2 * AV_AMAT + off, pvh + go);
            cpasync16(sb + 2 * AV_AMAT + AV_BMAT + off, pvl + go);
        }
    };

    float acc[2][8][4];
    #pragma unroll
    for (int i = 0; i < 2; i++)
        #pragma unroll
        for (int j = 0; j < 8; j++)
            #pragma unroll
            for (int k = 0; k < 4; k++) acc[i][j][k] = 0.0f;

    const int nch = Lz / 32;   // 32
    prefetch(0, 0); CP_COMMIT();
    prefetch(1, 1); CP_COMMIT();

    for (int c = 0; c < nch; c++) {
        if (c + 1 < nch) { CP_WAIT1(); } else { CP_WAIT0(); }
        __syncthreads();

        const uint32_t sb  = sbase + (c & 1) * AV_STAGE;
        const uint32_t sAh = sb;
        const uint32_t sAl = sb + AV_AMAT;
        const uint32_t sBh = sb + 2 * AV_AMAT;
        const uint32_t sBl = sBh + AV_BMAT;

        #pragma unroll
        for (int kk = 0; kk < 32; kk += 16) {
            const uint32_t kb = kk * 2;

            uint32_t bH[8][2], bL[8][2];
            #pragma unroll
            for (int nt = 0; nt < 8; nt++) {
                const uint32_t ro = (nt * 8) * AROW + kb + bOff;
                ldsm_x2(bH[nt], sBh + ro);
                ldsm_x2(bL[nt], sBl + ro);
            }

            #pragma unroll
            for (int mt = 0; mt < 2; mt++) {
                const uint32_t ro = (wm + mt * 16) * AROW + kb + aOff;
                uint32_t aH[4], aL[4];
                ldsm_x4(aH, sAh + ro);
                ldsm_x4(aL, sAl + ro);

                #pragma unroll
                for (int nt = 0; nt < 8; nt++) {
                    hmma(acc[mt][nt], aH, bH[nt]);
                    hmma(acc[mt][nt], aH, bL[nt]);
                    hmma(acc[mt][nt], aL, bH[nt]);
                }
            }
        }

        __syncthreads();
        if (c + 2 < nch) { prefetch(c + 2, (c & 1)); CP_COMMIT(); }
        else { CP_COMMIT(); }
    }

    const int b = z >> 4, h = z & 15;
    #pragma unroll
    for (int mt = 0; mt < 2; mt++) {
        const int m0 = bm + wm + mt * 16 + g;
        #pragma unroll
        for (int nt = 0; nt < 8; nt++) {
            const int n0 = nt * 8 + 2 * t;
            const size_t i0 = ((size_t)(b * Lz + m0)     << 10) + h * HDz + n0;
            const size_t i1 = ((size_t)(b * Lz + m0 + 8) << 10) + h * HDz + n0;
            __nv_bfloat162 lo;
            __nv_bfloat162 hi = split_hi2(acc[mt][nt][0], acc[mt][nt][1], lo);
            *(__nv_bfloat162*)&Ch[i0] = hi;
            *(__nv_bfloat162*)&Cl[i0] = lo;
            hi = split_hi2(acc[mt][nt][2], acc[mt][nt][3], lo);
            *(__nv_bfloat162*)&Ch[i1] = hi;
            *(__nv_bfloat162*)&Cl[i1] = lo;
        }
    }
}

// ---------------- softmax fused with bf16 split -----------------------------------
__global__ __launch_bounds__(256) void softmax_split_kernel(
    float* __restrict__ attn, __nv_bfloat16* __restrict__ ah,
    __nv_bfloat16* __restrict__ al)
{
    const size_t row = blockIdx.x;
    float4* p = reinterpret_cast<float4*>(attn + row * Lz);
    const int tid = threadIdx.x;
    __shared__ float red[8];

    float4 v = p[tid];
    float m = fmaxf(fmaxf(v.x, v.y), fmaxf(v.z, v.w));
    #pragma unroll
    for (int o = 16; o > 0; o >>= 1) m = fmaxf(m, __shfl_xor_sync(0xFFFFFFFFu, m, o));
    if ((tid & 31) == 0) red[tid >> 5] = m;
    __syncthreads();
    m = red[0];
    #pragma unroll
    for (int i = 1; i < 8; i++) m = fmaxf(m, red[i]);
    __syncthreads();

    v.x = __expf(v.x - m); v.y = __expf(v.y - m);
    v.z = __expf(v.z - m); v.w = __expf(v.w - m);
    float s = v.x + v.y + v.z + v.w;
    #pragma unroll
    for (int o = 16; o > 0; o >>= 1) s += __shfl_xor_sync(0xFFFFFFFFu, s, o);
    if ((tid & 31) == 0) red[tid >> 5] = s;
    __syncthreads();
    s = red[0];
    #pragma unroll
    for (int i = 1; i < 8; i++) s += red[i];

    float inv = 1.0f / s;
    v.x *= inv; v.y *= inv; v.z *= inv; v.w *= inv;
    p[tid] = v;

    __nv_bfloat162* H = reinterpret_cast<__nv_bfloat162*>(ah + row * Lz);
    __nv_bfloat162* L = reinterpret_cast<__nv_bfloat162*>(al + row * Lz);
    __nv_bfloat162 lo;
    __nv_bfloat162 hi = split_hi2(v.x, v.y, lo);
    H[tid * 2]     = hi; L[tid * 2]     = lo;
    hi = split_hi2(v.z, v.w, lo);
    H[tid * 2 + 1] = hi; L[tid * 2 + 1] = lo;
}

// ---------------- V transpose + split ----------------------------------------------
__global__ __launch_bounds__(256) void tsplit_v(
    const float* __restrict__ v, __nv_bfloat16* __restrict__ vth,
    __nv_bfloat16* __restrict__ vtl)
{
    __shared__ float tile[32][33];
    const int z  = blockIdx.z;
    const int l0 = blockIdx.x * 32;
    const int d0 = blockIdx.y * 32;
    const int tx = threadIdx.x & 31;
    const int ty = threadIdx.x >> 5;

    const float* src = v + (size_t)z * Lz * HDz;
    #pragma unroll
    for (int j = 0; j < 4; j++)
        tile[ty + j * 8][tx] = src[(size_t)(l0 + ty + j * 8) * HDz + d0 + tx];
    __syncthreads();

    __nv_bfloat16* dh = vth + (size_t)z * HDz * Lz;
    __nv_bfloat16* dl = vtl + (size_t)z * HDz * Lz;
    #pragma unroll
    for (int j = 0; j < 4; j++) {
        const float val = tile[tx][ty + j * 8];
        const __nv_bfloat16 h = __float2bfloat16(val);
        const size_t o = (size_t)(d0 + ty + j * 8) * Lz + l0 + tx;
        dh[o] = h;
        dl[o] = __float2bfloat16(val - __bfloat162float(h));
    }
}

// ---------------- misc small kernels ------------------------------------------------
__global__ __launch_bounds__(256) void split_kernel(
    const float* __restrict__ in, __nv_bfloat16* __restrict__ hi,
    __nv_bfloat16* __restrict__ lo, int n4)
{
    int i = blockIdx.x * (blockDim.x * 4) + threadIdx.x;
    #pragma unroll
    for (int u = 0; u < 4; u++, i += 256) {
        if (i < n4) {
            float4 v = ((const float4*)in)[i];
            __nv_bfloat162* H = (__nv_bfloat162*)hi;
            __nv_bfloat162* L = (__nv_bfloat162*)lo;
            __nv_bfloat162 l2;
            H[i*2+0] = split_hi2(v.x, v.y, l2); L[i*2+0] = l2;
            H[i*2+1] = split_hi2(v.z, v.w, l2); L[i*2+1] = l2;
        }
    }
}

__global__ void bias_kernel(const float* __restrict__ field,
                            const float* __restrict__ strength,
                            float* __restrict__ bias)
{
    int m = blockIdx.x * blockDim.x + threadIdx.x;
    if (m < Lz) {
        const float pi = 3.14159265358979323846f;
        float acc = 0.0f;
        #pragma unroll
        for (int i = 0; i < ORDERz; i++) {
            float sig = 1.0f / (1.0f + expf(-field[i * Lz + m]));
            acc += strength[i] * sinf((float)m * (float)(i + 1) * pi / (float)Lz) * sig;
        }
        bias[m] = acc;
    }
}

__global__ void energy_kernel(const float* __restrict__ s, float* __restrict__ e)
{
    e[0] = (s[0] * s[0] + s[1] * s[1] + s[2] * s[2]) * (1.0f / 3.0f);
}

// ---------------- launch --------------------------------------------------------------
extern "C" void kernel_launch(void* const* d_in, const int* in_sizes, int n_in,
                              void* d_out, int out_size)
{
    const float* x  = (const float*)d_in[0];
    const float* Wq = (const float*)d_in[1];
    const float* bq = (const float*)d_in[2];
    const float* Wk = (const float*)d_in[3];
    const float* bk = (const float*)d_in[4];
    const float* Wv = (const float*)d_in[5];
    const float* bv = (const float*)d_in[6];
    const float* Wo = (const float*)d_in[7];
    const float* bo = (const float*)d_in[8];
    const float* tf = (const float*)d_in[9];
    const float* ts = (const float*)d_in[10];

    float* out    = (float*)d_out;
    float* attn   = out + (size_t)Bz * Lz * Dz;
    float* energy = attn + (size_t)ZN * Lz * Lz;

    float *gv, *gbias;
    cudaGetSymbolAddress((void**)&gv,    g_v);
    cudaGetSymbolAddress((void**)&gbias, g_bias);

    __nv_bfloat16 *xh, *xl, *wh, *wl, *qh, *ql, *kh, *kl, *vth, *vtl, *ah, *al, *ch, *cl;
    cudaGetSymbolAddress((void**)&xh,  g_xh);
    cudaGetSymbolAddress((void**)&xl,  g_xl);
    cudaGetSymbolAddress((void**)&wh,  g_wh);
    cudaGetSymbolAddress((void**)&wl,  g_wl);
    cudaGetSymbolAddress((void**)&qh,  g_qh);
    cudaGetSymbolAddress((void**)&ql,  g_ql);
    cudaGetSymbolAddress((void**)&kh,  g_kh);
    cudaGetSymbolAddress((void**)&kl,  g_kl);
    cudaGetSymbolAddress((void**)&vth, g_vth);
    cudaGetSymbolAddress((void**)&vtl, g_vtl);
    cudaGetSymbolAddress((void**)&ah,  g_ah);
    cudaGetSymbolAddress((void**)&al,  g_al);
    cudaGetSymbolAddress((void**)&ch,  g_ch);
    cudaGetSymbolAddress((void**)&cl,  g_cl);

    cudaFuncSetAttribute(hmma_gemm<0>, cudaFuncAttributeMaxDynamicSharedMemorySize, HSMEM);
    cudaFuncSetAttribute(hmma_gemm<1>, cudaFuncAttributeMaxDynamicSharedMemorySize, HSMEM);
    cudaFuncSetAttribute(hmma_gemm<2>, cudaFuncAttributeMaxDynamicSharedMemorySize, HSMEM);
    cudaFuncSetAttribute(scores_hmma,  cudaFuncAttributeMaxDynamicSharedMemorySize, SSMEM);
    cudaFuncSetAttribute(av_hmma,      cudaFuncAttributeMaxDynamicSharedMemorySize, AVSMEM);

    bias_kernel<<<4, 256>>>(tf, ts, gbias);
    energy_kernel<<<1, 1>>>(ts, energy);

    const size_t WN = (size_t)Dz * Dz;
    split_kernel<<<(Mz*Dz/4 + 1023)/1024, 256>>>(x,  xh, xl, Mz*Dz/4);
    split_kernel<<<(WN/4 + 1023)/1024, 256>>>(Wq, wh + 0*WN, wl + 0*WN, WN/4);
    split_kernel<<<(WN/4 + 1023)/1024, 256>>>(Wk, wh + 1*WN, wl + 1*WN, WN/4);
    split_kernel<<<(WN/4 + 1023)/1024, 256>>>(Wv, wh + 2*WN, wl + 2*WN, WN/4);
    split_kernel<<<(WN/4 + 1023)/1024, 256>>>(Wo, wh + 3*WN, wl + 3*WN, WN/4);

    dim3 gproj(Dz / 128, Mz / 128);   // (8, 32) = 256 CTAs, single wave @ 2/SM
    hmma_gemm<2><<<gproj, 256, HSMEM>>>(xh, xl, wh + 0*WN, wl + 0*WN, bq, nullptr, qh, ql, Dz, Dz, 1.0f);
    hmma_gemm<2><<<gproj, 256, HSMEM>>>(xh, xl, wh + 1*WN, wl + 1*WN, bk, nullptr, kh, kl, Dz, Dz, 1.0f);
    hmma_gemm<1><<<gproj, 256, HSMEM>>>(xh, xl, wh + 2*WN, wl + 2*WN, bv, gv, nullptr, nullptr, Dz, Dz, 1.0f);

    tsplit_v<<<dim3(Lz/32, HDz/32, ZN), 256>>>(gv, vth, vtl);

    scores_hmma<<<dim3(8, 8, ZN), 256, SSMEM>>>(qh, ql, kh, kl, gbias, attn);

    softmax_split_kernel<<<ZN * Lz, 256>>>(attn, ah, al);

    av_hmma<<<dim3(1, Lz/256, ZN), 256, AVSMEM>>>(ah, al, vth, vtl, ch, cl);

    hmma_gemm<0><<<gproj, 256, HSMEM>>>(ch, cl, wh + 3*WN, wl + 3*WN, bo, out, nullptr, nullptr, Dz, Dz, 1.0f);
}